// round 13
// baseline (speedup 1.0000x reference)
#include <cuda_runtime.h>
#include <cuda_fp16.h>
#include <cstdint>
#include <math.h>

// Problem constants
#define B_SZ   2
#define S_LEN  2048
#define EMB    1024
#define NHEAD  16
#define HDIM   64
#define ROWS   (B_SZ * S_LEN)          // 4096

// Scratch (device globals -> no allocation). All fp16 operand tensors.
__device__ __half g_Qh [B_SZ * NHEAD * S_LEN * HDIM];   // [b,h,s,d]
__device__ __half g_Kh [B_SZ * NHEAD * S_LEN * HDIM];   // [b,h,s,d]
__device__ __half g_Vth[B_SZ * NHEAD * HDIM * S_LEN];   // [b,h,d,s]  (transposed!)
__device__ __half g_CTXh[ROWS * EMB];
__device__ __half g_Xh  [ROWS * EMB];
__device__ __half g_WaTh[3 * EMB * EMB];                // w_attn^T [3072][1024]
__device__ __half g_WpTh[EMB * EMB];                    // w_proj^T [1024][1024]

// ---------------------------------------------------------------------------
// Helpers
// ---------------------------------------------------------------------------
__device__ __forceinline__ uint32_t smem_u32(const void* p) {
    uint32_t a;
    asm("{ .reg .u64 t; cvta.to.shared.u64 t, %1; cvt.u32.u64 %0, t; }"
        : "=r"(a) : "l"(p));
    return a;
}
__device__ __forceinline__ void cp16(uint32_t smaddr, const void* gaddr) {
    asm volatile("cp.async.cg.shared.global [%0], [%1], 16;"
                 :: "r"(smaddr), "l"(gaddr) : "memory");
}
__device__ __forceinline__ uint32_t h2u(__half2 h) {
    return *reinterpret_cast<uint32_t*>(&h);
}
__device__ __forceinline__ float ex2(float x) {
    float y;
    asm("ex2.approx.ftz.f32 %0, %1;" : "=f"(y) : "f"(x));
    return y;
}
__device__ __forceinline__ void mma_f16(float& d0, float& d1, float& d2, float& d3,
                                        uint32_t a0, uint32_t a1, uint32_t a2, uint32_t a3,
                                        uint32_t b0, uint32_t b1) {
    asm volatile(
        "mma.sync.aligned.m16n8k16.row.col.f32.f16.f16.f32 "
        "{%0,%1,%2,%3},{%4,%5,%6,%7},{%8,%9},{%0,%1,%2,%3};"
        : "+f"(d0), "+f"(d1), "+f"(d2), "+f"(d3)
        : "r"(a0), "r"(a1), "r"(a2), "r"(a3), "r"(b0), "r"(b1));
}
#define LDSM_X4(r0, r1, r2, r3, addr)                                          \
    asm volatile("ldmatrix.sync.aligned.m8n8.x4.shared.b16 {%0,%1,%2,%3}, [%4];" \
                 : "=r"(r0), "=r"(r1), "=r"(r2), "=r"(r3) : "r"(addr))

// XOR swizzle within a 128B row: 16B chunk index ^ (row & 7)
__device__ __forceinline__ uint32_t swz(int row, int bc) {
    return (uint32_t)(row * 128 + (((bc >> 4) ^ (row & 7)) << 4) + (bc & 15));
}

// ---------------------------------------------------------------------------
// Fused prep: x -> fp16 copy, plus both weight transposes (fp32->fp16).
// ---------------------------------------------------------------------------
#define PREP_CVT_BLOCKS 4096
#define PREP_WA_BLOCKS  3072
#define PREP_WP_BLOCKS  1024
#define PREP_BLOCKS (PREP_CVT_BLOCKS + PREP_WA_BLOCKS + PREP_WP_BLOCKS)

__global__ void prep_all(const float* __restrict__ x,
                         const float* __restrict__ w_attn,
                         const float* __restrict__ w_proj)
{
    const int bid = blockIdx.x;
    if (bid < PREP_CVT_BLOCKS) {
        int i = (bid * 256 + threadIdx.x) * 4;
        float4 v = *(const float4*)(x + i);
        __half2* o = (__half2*)(g_Xh + i);
        o[0] = __floats2half2_rn(v.x, v.y);
        o[1] = __floats2half2_rn(v.z, v.w);
        return;
    }
    __shared__ float t[32][33];
    const float* src;
    __half* dst;
    int N, nblk_x, tb;
    if (bid < PREP_CVT_BLOCKS + PREP_WA_BLOCKS) {
        tb = bid - PREP_CVT_BLOCKS;
        src = w_attn; dst = g_WaTh; N = 3 * EMB; nblk_x = (3 * EMB) / 32;
    } else {
        tb = bid - PREP_CVT_BLOCKS - PREP_WA_BLOCKS;
        src = w_proj; dst = g_WpTh; N = EMB; nblk_x = EMB / 32;
    }
    const int K = EMB;
    const int x_ = threadIdx.x & 31, y_ = threadIdx.x >> 5;
    const int n0 = (tb % nblk_x) * 32, k0 = (tb / nblk_x) * 32;
#pragma unroll
    for (int i = 0; i < 4; i++)
        t[y_ + i * 8][x_] = src[(size_t)(k0 + y_ + i * 8) * N + n0 + x_];
    __syncthreads();
#pragma unroll
    for (int i = 0; i < 4; i++)
        dst[(size_t)(n0 + y_ + i * 8) * K + k0 + x_] = __float2half_rn(t[x_][y_ + i * 8]);
}

// ---------------------------------------------------------------------------
// fp16 mma.sync GEMM (R10/R12-proven) + persistent grid-stride tiles.
// CTA 128x128, 8 warps (2x4, warp 64x32), TK=64, 3-stage cp.async.
// ---------------------------------------------------------------------------
#define CMM 128
#define CNN 128
#define TKK 64
#define A_BY (CMM * TKK * 2)            // 16384
#define STG_B (2 * A_BY)                // 32768
#define SPIPE 3
#define GSMEM_BYTES (SPIPE * STG_B)     // 98304
#define NSTAGE (EMB / TKK)              // 16
#define GRID_PERSIST 296                // 148 SMs * 2 CTA

template <int MODE>
__global__ void __launch_bounds__(256, 2)
gemm_h(const float* __restrict__ bias, float* __restrict__ Cout)
{
    extern __shared__ char smc[];
    const uint32_t sb = smem_u32(smc);
    const int tid  = threadIdx.x;
    const int wid  = tid >> 5;
    const int lane = tid & 31;
    const int gid  = lane >> 2;
    const int tig  = lane & 3;
    const int warp_m = (wid >> 2) * 64;
    const int warp_n = (wid & 3) * 32;

    const __half* A  = (MODE == 1) ? g_CTXh : g_Xh;
    const __half* BT = (MODE == 1) ? g_WpTh : g_WaTh;

    const int NX = (MODE == 1) ? 8 : 24;
    const int NT = (MODE == 1) ? 256 : 768;

    const int lsel  = lane >> 3;
    const int lrow8 = lane & 7;
    const int aRowL   = warp_m + ((lsel & 1) << 3) + lrow8;
    const int aColOff = (lsel >> 1) << 4;
    const int bRowL   = warp_n + ((lsel >> 1) << 3) + lrow8;
    const int bColOff = (lsel & 1) << 4;

    const int lrow = tid >> 1;
    const int cb   = (tid & 1) * 4;

    for (int t = blockIdx.x; t < NT; t += gridDim.x) {
        const int m0 = (t / NX) * CMM;
        const int n0 = (t % NX) * CNN;

        float acc[4][4][4];
#pragma unroll
        for (int mt = 0; mt < 4; mt++)
#pragma unroll
            for (int nt = 0; nt < 4; nt++)
#pragma unroll
                for (int r = 0; r < 4; r++) acc[mt][nt][r] = 0.0f;

        const __half* gA = A  + (size_t)(m0 + lrow) * EMB;
        const __half* gB = BT + (size_t)(n0 + lrow) * EMB;

#define ISSUE(s_)                                                              \
        {                                                                      \
            uint32_t st = sb + (uint32_t)(((s_) % SPIPE) * STG_B);             \
            const __half* ga = gA + (s_) * TKK;                                \
            const __half* gb = gB + (s_) * TKK;                                \
            _Pragma("unroll")                                                  \
            for (int c = 0; c < 4; c++) {                                      \
                cp16(st + swz(lrow, (cb + c) * 16), ga + (cb + c) * 8);        \
                cp16(st + A_BY + swz(lrow, (cb + c) * 16), gb + (cb + c) * 8); \
            }                                                                  \
        }

        ISSUE(0); asm volatile("cp.async.commit_group;" ::: "memory");
        ISSUE(1); asm volatile("cp.async.commit_group;" ::: "memory");
        asm volatile("cp.async.wait_group 1;" ::: "memory");
        __syncthreads();

        for (int s = 0; s < NSTAGE; s++) {
            if (s + 2 < NSTAGE) ISSUE(s + 2);
            asm volatile("cp.async.commit_group;" ::: "memory");

            const uint32_t stA = sb + (uint32_t)((s % SPIPE) * STG_B);
            const uint32_t stB = stA + A_BY;
#pragma unroll
            for (int g = 0; g < 4; g++) {
                const int bc = 32 * g;
                uint32_t af[4][4], bf[2][4];
#pragma unroll
                for (int mt = 0; mt < 4; mt++)
                    LDSM_X4(af[mt][0], af[mt][1], af[mt][2], af[mt][3],
                            stA + swz(aRowL + mt * 16, bc + aColOff));
#pragma unroll
                for (int np = 0; np < 2; np++)
                    LDSM_X4(bf[np][0], bf[np][1], bf[np][2], bf[np][3],
                            stB + swz(bRowL + np * 16, bc + bColOff));
#pragma unroll
                for (int mt = 0; mt < 4; mt++)
#pragma unroll
                    for (int nt = 0; nt < 4; nt++)
                        mma_f16(acc[mt][nt][0], acc[mt][nt][1],
                                acc[mt][nt][2], acc[mt][nt][3],
                                af[mt][0], af[mt][1], af[mt][2], af[mt][3],
                                bf[nt >> 1][(nt & 1) * 2], bf[nt >> 1][(nt & 1) * 2 + 1]);
            }
            asm volatile("cp.async.wait_group 1;" ::: "memory");
            __syncthreads();
        }
#undef ISSUE

#pragma unroll
        for (int mt = 0; mt < 4; mt++) {
            const int r0 = m0 + warp_m + mt * 16 + gid;
            const int r1 = r0 + 8;
#pragma unroll
            for (int nt = 0; nt < 4; nt++) {
                const int nb = n0 + warp_n + nt * 8;
                const int c  = nb + tig * 2;
                const float2 bv = *(const float2*)(bias + c);
                float2 o0, o1;
                o0.x = acc[mt][nt][0] + bv.x;
                o0.y = acc[mt][nt][1] + bv.y;
                o1.x = acc[mt][nt][2] + bv.x;
                o1.y = acc[mt][nt][3] + bv.y;
                if (MODE == 1) {
                    *(float2*)(Cout + (size_t)r0 * EMB + c) = o0;
                    *(float2*)(Cout + (size_t)r1 * EMB + c) = o1;
                } else {
                    const int which = nb >> 10;
                    const int e  = nb & 1023;
                    const int h  = e >> 6;
                    const int dd = (e & 63) + tig * 2;
                    const int b0i = r0 >> 11, s0i = r0 & 2047;
                    const int b1i = r1 >> 11, s1i = r1 & 2047;
                    if (which == 2) {
                        __half* vb0 = g_Vth + ((size_t)(b0i * NHEAD + h) * HDIM + dd) * S_LEN;
                        __half* vb1 = g_Vth + ((size_t)(b1i * NHEAD + h) * HDIM + dd) * S_LEN;
                        vb0[s0i]          = __float2half_rn(o0.x);
                        vb0[S_LEN + s0i]  = __float2half_rn(o0.y);
                        vb1[s1i]          = __float2half_rn(o1.x);
                        vb1[S_LEN + s1i]  = __float2half_rn(o1.y);
                    } else {
                        __half* dst = (which == 0) ? g_Qh : g_Kh;
                        *(__half2*)(dst + ((size_t)(b0i * NHEAD + h) * S_LEN + s0i) * HDIM + dd)
                            = __floats2half2_rn(o0.x, o0.y);
                        *(__half2*)(dst + ((size_t)(b1i * NHEAD + h) * S_LEN + s1i) * HDIM + dd)
                            = __floats2half2_rn(o1.x, o1.y);
                    }
                }
            }
        }
    }
}

// ---------------------------------------------------------------------------
// Flash attention (causal), fp16 mma + ldmatrix, base-2 softmax (MUFU).
// CTA 256 thr / 8 warps, q-tile 128, LOAD tile 128 keys (2 x 64-key halves),
// 2 smem buffers (80KB total -> still 2 CTA/SM). Rescale skipped via warp
// vote when running max unchanged.
// ---------------------------------------------------------------------------
#define FQ_BY (128 * 128)               // Q tile 16KB
#define KT_BY (128 * 128)               // K tile: 128 key-rows x 128B = 16KB
#define VT_BY (128 * 128)               // V tile: 2 halves x 64 d-rows x 128B
#define KOFF  FQ_BY
#define VOFF  (FQ_BY + 2 * KT_BY)
#define FLASH_SMEM (FQ_BY + 2 * KT_BY + 2 * VT_BY)      // 81920

#define SCALE2 0.18033688011112042f     // 0.125 * log2(e)

__global__ void __launch_bounds__(256, 2)
flash_h()
{
    extern __shared__ char smc[];
    const uint32_t sb = smem_u32(smc);
    const int tid  = threadIdx.x;
    const int wid  = tid >> 5;
    const int lane = tid & 31;
    const int gid  = lane >> 2;
    const int tig  = lane & 3;
    const int qt   = gridDim.x - 1 - blockIdx.x;   // heavy tiles first
    const int bh   = blockIdx.y;
    const int q0   = qt * 128;

    const __half* Qg = g_Qh  + (size_t)bh * S_LEN * HDIM;
    const __half* Kg = g_Kh  + (size_t)bh * S_LEN * HDIM;
    const __half* Vg = g_Vth + (size_t)bh * HDIM * S_LEN;

    const int lsel  = lane >> 3;
    const int lrow8 = lane & 7;
    const int aRow    = wid * 16 + ((lsel & 1) << 3) + lrow8;
    const int aColOff = (lsel >> 1) << 4;
    const int bRow    = ((lsel >> 1) << 3) + lrow8;
    const int bColOff = (lsel & 1) << 4;

    // Q load (group 0, together with first KV tile)
    {
        const int r = tid >> 1, c0 = (tid & 1) * 4;
        const __half* gq = Qg + (size_t)(q0 + r) * HDIM;
#pragma unroll
        for (int c = 0; c < 4; c++)
            cp16(sb + swz(r, (c0 + c) * 16), gq + (c0 + c) * 8);
    }

    // Load 128 keys of K and V (V as two 64-key half-tiles) into buffer buf_.
#define ISSUE_KV2(it_)                                                         \
    {                                                                          \
        const int buf_ = (it_) & 1;                                            \
        const int r = tid >> 1, c0 = (tid & 1) * 4;                            \
        const __half* gk = Kg + (size_t)((it_) * 128 + r) * HDIM;              \
        const int half_ = r >> 6, dv_ = r & 63;                                \
        const __half* gv = Vg + (size_t)dv_ * S_LEN + (it_) * 128 + half_ * 64;\
        _Pragma("unroll")                                                      \
        for (int c = 0; c < 4; c++) {                                          \
            cp16(sb + KOFF + buf_ * KT_BY + swz(r, (c0 + c) * 16),             \
                 gk + (c0 + c) * 8);                                           \
            cp16(sb + VOFF + buf_ * VT_BY + half_ * 8192 + swz(dv_, (c0 + c) * 16), \
                 gv + (c0 + c) * 8);                                           \
        }                                                                      \
    }

    const int nit = qt + 1;            // 128-key iterations

    ISSUE_KV2(0);
    asm volatile("cp.async.commit_group;" ::: "memory");
    asm volatile("cp.async.wait_group 0;" ::: "memory");
    __syncthreads();

    // Q A-fragments via ldmatrix
    uint32_t qa[4][4];
#pragma unroll
    for (int g = 0; g < 4; g++)
        LDSM_X4(qa[g][0], qa[g][1], qa[g][2], qa[g][3],
                sb + swz(aRow, 32 * g + aColOff));

    float m0v = -1e30f, m1v = -1e30f, l0 = 0.0f, l1 = 0.0f;
    float o[8][4];
#pragma unroll
    for (int nt = 0; nt < 8; nt++)
#pragma unroll
        for (int r = 0; r < 4; r++) o[nt][r] = 0.0f;

    const int r0g = q0 + wid * 16 + gid;

    for (int it = 0; it < nit; it++) {
        if (it > 0) {
            asm volatile("cp.async.wait_group 0;" ::: "memory");
            __syncthreads();           // buf it ready; all warps done with it-1
        }
        if (it + 1 < nit) {
            ISSUE_KV2(it + 1);
            asm volatile("cp.async.commit_group;" ::: "memory");
        }

        const uint32_t Kb = sb + KOFF + (uint32_t)((it & 1) * KT_BY);
        const uint32_t Vb = sb + VOFF + (uint32_t)((it & 1) * VT_BY);

#pragma unroll
        for (int h = 0; h < 2; h++) {
            const uint32_t Ks = Kb + (uint32_t)h * 8192;
            const uint32_t Vs = Vb + (uint32_t)h * 8192;
            const int k0 = it * 128 + h * 64;

            float s[8][4];
#pragma unroll
            for (int nt = 0; nt < 8; nt++)
#pragma unroll
                for (int r = 0; r < 4; r++) s[nt][r] = 0.0f;

#pragma unroll
            for (int g = 0; g < 4; g++) {
                const int bc = 32 * g;
#pragma unroll
                for (int np = 0; np < 4; np++) {
                    uint32_t bf[4];
                    LDSM_X4(bf[0], bf[1], bf[2], bf[3],
                            Ks + swz(bRow + np * 16, bc + bColOff));
                    mma_f16(s[2 * np][0], s[2 * np][1], s[2 * np][2], s[2 * np][3],
                            qa[g][0], qa[g][1], qa[g][2], qa[g][3], bf[0], bf[1]);
                    mma_f16(s[2 * np + 1][0], s[2 * np + 1][1],
                            s[2 * np + 1][2], s[2 * np + 1][3],
                            qa[g][0], qa[g][1], qa[g][2], qa[g][3], bf[2], bf[3]);
                }
            }

            const bool domask = (k0 + 63) > r0g;
#pragma unroll
            for (int nt = 0; nt < 8; nt++) {
                const int c0 = k0 + nt * 8 + tig * 2;
                s[nt][0] *= SCALE2; s[nt][1] *= SCALE2;
                s[nt][2] *= SCALE2; s[nt][3] *= SCALE2;
                if (domask) {
                    if (c0 > r0g)         s[nt][0] = -1e30f;
                    if (c0 + 1 > r0g)     s[nt][1] = -1e30f;
                    if (c0 > r0g + 8)     s[nt][2] = -1e30f;
                    if (c0 + 1 > r0g + 8) s[nt][3] = -1e30f;
                }
            }

            float mx0 = -1e30f, mx1 = -1e30f;
#pragma unroll
            for (int nt = 0; nt < 8; nt++) {
                mx0 = fmaxf(mx0, fmaxf(s[nt][0], s[nt][1]));
                mx1 = fmaxf(mx1, fmaxf(s[nt][2], s[nt][3]));
            }
            mx0 = fmaxf(mx0, __shfl_xor_sync(0xffffffffu, mx0, 1));
            mx0 = fmaxf(mx0, __shfl_xor_sync(0xffffffffu, mx0, 2));
            mx1 = fmaxf(mx1, __shfl_xor_sync(0xffffffffu, mx1, 1));
            mx1 = fmaxf(mx1, __shfl_xor_sync(0xffffffffu, mx1, 2));

            const float mn0 = fmaxf(m0v, mx0);
            const float mn1 = fmaxf(m1v, mx1);
            const float al0 = ex2(m0v - mn0);
            const float al1 = ex2(m1v - mn1);
            m0v = mn0; m1v = mn1;

            uint32_t ph[8][2];
            float sum0 = 0.0f, sum1 = 0.0f;
#pragma unroll
            for (int nt = 0; nt < 8; nt++) {
                __half2 h01 = __floats2half2_rn(ex2(s[nt][0] - mn0),
                                                ex2(s[nt][1] - mn0));
                __half2 h23 = __floats2half2_rn(ex2(s[nt][2] - mn1),
                                                ex2(s[nt][3] - mn1));
                ph[nt][0] = h2u(h01);
                ph[nt][1] = h2u(h23);
                float2 f01 = __half22float2(h01);
                float2 f23 = __half22float2(h23);
                sum0 += f01.x + f01.y;
                sum1 += f23.x + f23.y;
            }
            sum0 += __shfl_xor_sync(0xffffffffu, sum0, 1);
            sum0 += __shfl_xor_sync(0xffffffffu, sum0, 2);
            sum1 += __shfl_xor_sync(0xffffffffu, sum1, 1);
            sum1 += __shfl_xor_sync(0xffffffffu, sum1, 2);
            l0 = l0 * al0 + sum0;
            l1 = l1 * al1 + sum1;

            // skip O rescale when no lane's max moved (alpha == 1 exactly)
            const bool resc = !__all_sync(0xffffffffu,
                                          (al0 == 1.0f) & (al1 == 1.0f));
            if (resc) {
#pragma unroll
                for (int nt = 0; nt < 8; nt++) {
                    o[nt][0] *= al0; o[nt][1] *= al0;
                    o[nt][2] *= al1; o[nt][3] *= al1;
                }
            }

#pragma unroll
            for (int g = 0; g < 4; g++) {
                const int bc = 32 * g;
#pragma unroll
                for (int np = 0; np < 4; np++) {
                    uint32_t bf[4];
                    LDSM_X4(bf[0], bf[1], bf[2], bf[3],
                            Vs + swz(bRow + np * 16, bc + bColOff));
                    mma_f16(o[2 * np][0], o[2 * np][1], o[2 * np][2], o[2 * np][3],
                            ph[2 * g][0], ph[2 * g][1],
                            ph[2 * g + 1][0], ph[2 * g + 1][1], bf[0], bf[1]);
                    mma_f16(o[2 * np + 1][0], o[2 * np + 1][1],
                            o[2 * np + 1][2], o[2 * np + 1][3],
                            ph[2 * g][0], ph[2 * g][1],
                            ph[2 * g + 1][0], ph[2 * g + 1][1], bf[2], bf[3]);
                }
            }
        }
    }
#undef ISSUE_KV2

    // write ctx fp16
    const int b = bh >> 4, h = bh & 15;
    const float inv0 = 1.0f / l0;
    const float inv1 = 1.0f / l1;
    const int r1g = r0g + 8;
#pragma unroll
    for (int nt = 0; nt < 8; nt++) {
        const int col = h * HDIM + nt * 8 + tig * 2;
        *(__half2*)(g_CTXh + ((size_t)(b * S_LEN + r0g)) * EMB + col)
            = __floats2half2_rn(o[nt][0] * inv0, o[nt][1] * inv0);
        *(__half2*)(g_CTXh + ((size_t)(b * S_LEN + r1g)) * EMB + col)
            = __floats2half2_rn(o[nt][2] * inv1, o[nt][3] * inv1);
    }
}

// ---------------------------------------------------------------------------
extern "C" void kernel_launch(void* const* d_in, const int* in_sizes, int n_in,
                              void* d_out, int out_size)
{
    const float* x      = (const float*)d_in[0];
    const float* w_attn = (const float*)d_in[1];
    const float* b_attn = (const float*)d_in[2];
    const float* w_proj = (const float*)d_in[3];
    const float* b_proj = (const float*)d_in[4];
    float* out = (float*)d_out;

    cudaFuncSetAttribute(gemm_h<0>, cudaFuncAttributeMaxDynamicSharedMemorySize, GSMEM_BYTES);
    cudaFuncSetAttribute(gemm_h<1>, cudaFuncAttributeMaxDynamicSharedMemorySize, GSMEM_BYTES);
    cudaFuncSetAttribute(flash_h,   cudaFuncAttributeMaxDynamicSharedMemorySize, FLASH_SMEM);

    // 0) fused prep: x->fp16 + both weight transposes
    prep_all<<<PREP_BLOCKS, 256>>>(x, w_attn, w_proj);

    // 1) QKV GEMM (persistent, 768 tiles over 296 CTAs)
    gemm_h<0><<<GRID_PERSIST, 256, GSMEM_BYTES>>>(b_attn, nullptr);

    // 2) causal flash attention -> g_CTXh
    flash_h<<<dim3(S_LEN / 128, B_SZ * NHEAD), 256, FLASH_SMEM>>>();

    // 3) projection GEMM (256 tiles < 296 slots, single wave)
    gemm_h<1><<<256, 256, GSMEM_BYTES>>>(b_proj, out);
}

// round 14
// speedup vs baseline: 1.0236x; 1.0236x over previous
#include <cuda_runtime.h>
#include <cuda_fp16.h>
#include <cstdint>
#include <math.h>

// Problem constants
#define B_SZ   2
#define S_LEN  2048
#define EMB    1024
#define NHEAD  16
#define HDIM   64
#define ROWS   (B_SZ * S_LEN)          // 4096

// Scratch (device globals -> no allocation). All fp16 operand tensors.
__device__ __half g_Qh [B_SZ * NHEAD * S_LEN * HDIM];   // [b,h,s,d]
__device__ __half g_Kh [B_SZ * NHEAD * S_LEN * HDIM];   // [b,h,s,d]
__device__ __half g_Vth[B_SZ * NHEAD * HDIM * S_LEN];   // [b,h,d,s]  (transposed!)
__device__ __half g_CTXh[ROWS * EMB];
__device__ __half g_Xh  [ROWS * EMB];
__device__ __half g_WaTh[3 * EMB * EMB];                // w_attn^T [3072][1024]
__device__ __half g_WpTh[EMB * EMB];                    // w_proj^T [1024][1024]

// ---------------------------------------------------------------------------
// Helpers
// ---------------------------------------------------------------------------
__device__ __forceinline__ uint32_t smem_u32(const void* p) {
    uint32_t a;
    asm("{ .reg .u64 t; cvta.to.shared.u64 t, %1; cvt.u32.u64 %0, t; }"
        : "=r"(a) : "l"(p));
    return a;
}
__device__ __forceinline__ void cp16(uint32_t smaddr, const void* gaddr) {
    asm volatile("cp.async.cg.shared.global [%0], [%1], 16;"
                 :: "r"(smaddr), "l"(gaddr) : "memory");
}
__device__ __forceinline__ uint32_t h2u(__half2 h) {
    return *reinterpret_cast<uint32_t*>(&h);
}
__device__ __forceinline__ float ex2(float x) {
    float y;
    asm("ex2.approx.ftz.f32 %0, %1;" : "=f"(y) : "f"(x));
    return y;
}
__device__ __forceinline__ void mma_f16(float& d0, float& d1, float& d2, float& d3,
                                        uint32_t a0, uint32_t a1, uint32_t a2, uint32_t a3,
                                        uint32_t b0, uint32_t b1) {
    asm volatile(
        "mma.sync.aligned.m16n8k16.row.col.f32.f16.f16.f32 "
        "{%0,%1,%2,%3},{%4,%5,%6,%7},{%8,%9},{%0,%1,%2,%3};"
        : "+f"(d0), "+f"(d1), "+f"(d2), "+f"(d3)
        : "r"(a0), "r"(a1), "r"(a2), "r"(a3), "r"(b0), "r"(b1));
}
#define LDSM_X4(r0, r1, r2, r3, addr)                                          \
    asm volatile("ldmatrix.sync.aligned.m8n8.x4.shared.b16 {%0,%1,%2,%3}, [%4];" \
                 : "=r"(r0), "=r"(r1), "=r"(r2), "=r"(r3) : "r"(addr))

// XOR swizzle within a 128B row: 16B chunk index ^ (row & 7)
__device__ __forceinline__ uint32_t swz(int row, int bc) {
    return (uint32_t)(row * 128 + (((bc >> 4) ^ (row & 7)) << 4) + (bc & 15));
}

// ---------------------------------------------------------------------------
// Fused prep: x -> fp16 copy, plus both weight transposes (fp32->fp16).
// ---------------------------------------------------------------------------
#define PREP_CVT_BLOCKS 4096
#define PREP_WA_BLOCKS  3072
#define PREP_WP_BLOCKS  1024
#define PREP_BLOCKS (PREP_CVT_BLOCKS + PREP_WA_BLOCKS + PREP_WP_BLOCKS)

__global__ void prep_all(const float* __restrict__ x,
                         const float* __restrict__ w_attn,
                         const float* __restrict__ w_proj)
{
    const int bid = blockIdx.x;
    if (bid < PREP_CVT_BLOCKS) {
        int i = (bid * 256 + threadIdx.x) * 4;
        float4 v = *(const float4*)(x + i);
        __half2* o = (__half2*)(g_Xh + i);
        o[0] = __floats2half2_rn(v.x, v.y);
        o[1] = __floats2half2_rn(v.z, v.w);
        return;
    }
    __shared__ float t[32][33];
    const float* src;
    __half* dst;
    int N, nblk_x, tb;
    if (bid < PREP_CVT_BLOCKS + PREP_WA_BLOCKS) {
        tb = bid - PREP_CVT_BLOCKS;
        src = w_attn; dst = g_WaTh; N = 3 * EMB; nblk_x = (3 * EMB) / 32;
    } else {
        tb = bid - PREP_CVT_BLOCKS - PREP_WA_BLOCKS;
        src = w_proj; dst = g_WpTh; N = EMB; nblk_x = EMB / 32;
    }
    const int K = EMB;
    const int x_ = threadIdx.x & 31, y_ = threadIdx.x >> 5;
    const int n0 = (tb % nblk_x) * 32, k0 = (tb / nblk_x) * 32;
#pragma unroll
    for (int i = 0; i < 4; i++)
        t[y_ + i * 8][x_] = src[(size_t)(k0 + y_ + i * 8) * N + n0 + x_];
    __syncthreads();
#pragma unroll
    for (int i = 0; i < 4; i++)
        dst[(size_t)(n0 + y_ + i * 8) * K + k0 + x_] = __float2half_rn(t[x_][y_ + i * 8]);
}

// ---------------------------------------------------------------------------
// fp16 mma.sync GEMM (R10/R12-proven) + persistent grid-stride tiles.
// CTA 128x128, 8 warps (2x4, warp 64x32), TK=64, 3-stage cp.async.
// ---------------------------------------------------------------------------
#define CMM 128
#define CNN 128
#define TKK 64
#define A_BY (CMM * TKK * 2)            // 16384
#define STG_B (2 * A_BY)                // 32768
#define SPIPE 3
#define GSMEM_BYTES (SPIPE * STG_B)     // 98304
#define NSTAGE (EMB / TKK)              // 16
#define GRID_PERSIST 296                // 148 SMs * 2 CTA

template <int MODE>
__global__ void __launch_bounds__(256, 2)
gemm_h(const float* __restrict__ bias, float* __restrict__ Cout)
{
    extern __shared__ char smc[];
    const uint32_t sb = smem_u32(smc);
    const int tid  = threadIdx.x;
    const int wid  = tid >> 5;
    const int lane = tid & 31;
    const int gid  = lane >> 2;
    const int tig  = lane & 3;
    const int warp_m = (wid >> 2) * 64;
    const int warp_n = (wid & 3) * 32;

    const __half* A  = (MODE == 1) ? g_CTXh : g_Xh;
    const __half* BT = (MODE == 1) ? g_WpTh : g_WaTh;

    const int NX = (MODE == 1) ? 8 : 24;
    const int NT = (MODE == 1) ? 256 : 768;

    const int lsel  = lane >> 3;
    const int lrow8 = lane & 7;
    const int aRowL   = warp_m + ((lsel & 1) << 3) + lrow8;
    const int aColOff = (lsel >> 1) << 4;
    const int bRowL   = warp_n + ((lsel >> 1) << 3) + lrow8;
    const int bColOff = (lsel & 1) << 4;

    const int lrow = tid >> 1;
    const int cb   = (tid & 1) * 4;

    for (int t = blockIdx.x; t < NT; t += gridDim.x) {
        const int m0 = (t / NX) * CMM;
        const int n0 = (t % NX) * CNN;

        float acc[4][4][4];
#pragma unroll
        for (int mt = 0; mt < 4; mt++)
#pragma unroll
            for (int nt = 0; nt < 4; nt++)
#pragma unroll
                for (int r = 0; r < 4; r++) acc[mt][nt][r] = 0.0f;

        const __half* gA = A  + (size_t)(m0 + lrow) * EMB;
        const __half* gB = BT + (size_t)(n0 + lrow) * EMB;

#define ISSUE(s_)                                                              \
        {                                                                      \
            uint32_t st = sb + (uint32_t)(((s_) % SPIPE) * STG_B);             \
            const __half* ga = gA + (s_) * TKK;                                \
            const __half* gb = gB + (s_) * TKK;                                \
            _Pragma("unroll")                                                  \
            for (int c = 0; c < 4; c++) {                                      \
                cp16(st + swz(lrow, (cb + c) * 16), ga + (cb + c) * 8);        \
                cp16(st + A_BY + swz(lrow, (cb + c) * 16), gb + (cb + c) * 8); \
            }                                                                  \
        }

        ISSUE(0); asm volatile("cp.async.commit_group;" ::: "memory");
        ISSUE(1); asm volatile("cp.async.commit_group;" ::: "memory");
        asm volatile("cp.async.wait_group 1;" ::: "memory");
        __syncthreads();

        for (int s = 0; s < NSTAGE; s++) {
            if (s + 2 < NSTAGE) ISSUE(s + 2);
            asm volatile("cp.async.commit_group;" ::: "memory");

            const uint32_t stA = sb + (uint32_t)((s % SPIPE) * STG_B);
            const uint32_t stB = stA + A_BY;
#pragma unroll
            for (int g = 0; g < 4; g++) {
                const int bc = 32 * g;
                uint32_t af[4][4], bf[2][4];
#pragma unroll
                for (int mt = 0; mt < 4; mt++)
                    LDSM_X4(af[mt][0], af[mt][1], af[mt][2], af[mt][3],
                            stA + swz(aRowL + mt * 16, bc + aColOff));
#pragma unroll
                for (int np = 0; np < 2; np++)
                    LDSM_X4(bf[np][0], bf[np][1], bf[np][2], bf[np][3],
                            stB + swz(bRowL + np * 16, bc + bColOff));
#pragma unroll
                for (int mt = 0; mt < 4; mt++)
#pragma unroll
                    for (int nt = 0; nt < 4; nt++)
                        mma_f16(acc[mt][nt][0], acc[mt][nt][1],
                                acc[mt][nt][2], acc[mt][nt][3],
                                af[mt][0], af[mt][1], af[mt][2], af[mt][3],
                                bf[nt >> 1][(nt & 1) * 2], bf[nt >> 1][(nt & 1) * 2 + 1]);
            }
            asm volatile("cp.async.wait_group 1;" ::: "memory");
            __syncthreads();
        }
#undef ISSUE

#pragma unroll
        for (int mt = 0; mt < 4; mt++) {
            const int r0 = m0 + warp_m + mt * 16 + gid;
            const int r1 = r0 + 8;
#pragma unroll
            for (int nt = 0; nt < 4; nt++) {
                const int nb = n0 + warp_n + nt * 8;
                const int c  = nb + tig * 2;
                const float2 bv = *(const float2*)(bias + c);
                float2 o0, o1;
                o0.x = acc[mt][nt][0] + bv.x;
                o0.y = acc[mt][nt][1] + bv.y;
                o1.x = acc[mt][nt][2] + bv.x;
                o1.y = acc[mt][nt][3] + bv.y;
                if (MODE == 1) {
                    *(float2*)(Cout + (size_t)r0 * EMB + c) = o0;
                    *(float2*)(Cout + (size_t)r1 * EMB + c) = o1;
                } else {
                    const int which = nb >> 10;
                    const int e  = nb & 1023;
                    const int h  = e >> 6;
                    const int dd = (e & 63) + tig * 2;
                    const int b0i = r0 >> 11, s0i = r0 & 2047;
                    const int b1i = r1 >> 11, s1i = r1 & 2047;
                    if (which == 2) {
                        __half* vb0 = g_Vth + ((size_t)(b0i * NHEAD + h) * HDIM + dd) * S_LEN;
                        __half* vb1 = g_Vth + ((size_t)(b1i * NHEAD + h) * HDIM + dd) * S_LEN;
                        vb0[s0i]          = __float2half_rn(o0.x);
                        vb0[S_LEN + s0i]  = __float2half_rn(o0.y);
                        vb1[s1i]          = __float2half_rn(o1.x);
                        vb1[S_LEN + s1i]  = __float2half_rn(o1.y);
                    } else {
                        __half* dst = (which == 0) ? g_Qh : g_Kh;
                        *(__half2*)(dst + ((size_t)(b0i * NHEAD + h) * S_LEN + s0i) * HDIM + dd)
                            = __floats2half2_rn(o0.x, o0.y);
                        *(__half2*)(dst + ((size_t)(b1i * NHEAD + h) * S_LEN + s1i) * HDIM + dd)
                            = __floats2half2_rn(o1.x, o1.y);
                    }
                }
            }
        }
    }
}

// ---------------------------------------------------------------------------
// Flash attention (causal), fp16 mma + ldmatrix. Base-2 softmax (raw MUFU).
// CTA 256 thr / 8 warps, q-tile 128, k-tile 64, D=64. K/V triple-buffered.
// R12 structure + warp-vote rescale skip (single change).
// ---------------------------------------------------------------------------
#define FQ_BY (128 * 128)               // Q tile 16KB
#define FK_BY (64 * 128)                // 8KB per K buffer
#define KOFF  FQ_BY
#define VOFF  (FQ_BY + 3 * FK_BY)
#define FLASH_SMEM (FQ_BY + 6 * FK_BY)  // 65536

#define SCALE2 0.18033688011112042f     // 0.125 * log2(e)

__global__ void __launch_bounds__(256, 2)
flash_h()
{
    extern __shared__ char smc[];
    const uint32_t sb = smem_u32(smc);
    const int tid  = threadIdx.x;
    const int wid  = tid >> 5;
    const int lane = tid & 31;
    const int gid  = lane >> 2;
    const int tig  = lane & 3;
    const int qt   = gridDim.x - 1 - blockIdx.x;   // heavy tiles first
    const int bh   = blockIdx.y;
    const int q0   = qt * 128;

    const __half* Qg = g_Qh  + (size_t)bh * S_LEN * HDIM;
    const __half* Kg = g_Kh  + (size_t)bh * S_LEN * HDIM;
    const __half* Vg = g_Vth + (size_t)bh * HDIM * S_LEN;

    const int lsel  = lane >> 3;
    const int lrow8 = lane & 7;
    const int aRow    = wid * 16 + ((lsel & 1) << 3) + lrow8;
    const int aColOff = (lsel >> 1) << 4;
    const int bRow    = ((lsel >> 1) << 3) + lrow8;
    const int bColOff = (lsel & 1) << 4;

    // Q load
    {
        const int r = tid >> 1, c0 = (tid & 1) * 4;
        const __half* gq = Qg + (size_t)(q0 + r) * HDIM;
#pragma unroll
        for (int c = 0; c < 4; c++)
            cp16(sb + swz(r, (c0 + c) * 16), gq + (c0 + c) * 8);
    }

#define ISSUE_KV(kt_)                                                          \
    {                                                                          \
        const int buf_ = (kt_) % 3;                                            \
        const int r = tid >> 2, c0 = (tid & 3) * 2;                            \
        const __half* gk = Kg + (size_t)((kt_) * 64 + r) * HDIM;               \
        const __half* gv = Vg + (size_t)r * S_LEN + (kt_) * 64;                \
        _Pragma("unroll")                                                      \
        for (int c = 0; c < 2; c++) {                                          \
            cp16(sb + KOFF + buf_ * FK_BY + swz(r, (c0 + c) * 16),             \
                 gk + (c0 + c) * 8);                                           \
            cp16(sb + VOFF + buf_ * FK_BY + swz(r, (c0 + c) * 16),             \
                 gv + (c0 + c) * 8);                                           \
        }                                                                      \
    }

    const int nkt = 2 * (qt + 1);

    ISSUE_KV(0);
    asm volatile("cp.async.commit_group;" ::: "memory");
    if (nkt > 1) ISSUE_KV(1);
    asm volatile("cp.async.commit_group;" ::: "memory");
    asm volatile("cp.async.wait_group 1;" ::: "memory");
    __syncthreads();

    uint32_t qa[4][4];
#pragma unroll
    for (int g = 0; g < 4; g++)
        LDSM_X4(qa[g][0], qa[g][1], qa[g][2], qa[g][3],
                sb + swz(aRow, 32 * g + aColOff));

    float m0v = -1e30f, m1v = -1e30f, l0 = 0.0f, l1 = 0.0f;
    float o[8][4];
#pragma unroll
    for (int nt = 0; nt < 8; nt++)
#pragma unroll
        for (int r = 0; r < 4; r++) o[nt][r] = 0.0f;

    const int r0g = q0 + wid * 16 + gid;

    for (int kt = 0; kt < nkt; kt++) {
        if (kt > 0) {
            asm volatile("cp.async.wait_group 1;" ::: "memory");
            __syncthreads();
        }
        if (kt + 2 < nkt) ISSUE_KV(kt + 2);
        asm volatile("cp.async.commit_group;" ::: "memory");

        const uint32_t Ks = sb + KOFF + (uint32_t)((kt % 3) * FK_BY);
        const uint32_t Vs = sb + VOFF + (uint32_t)((kt % 3) * FK_BY);
        const int k0 = kt * 64;

        float s[8][4];
#pragma unroll
        for (int nt = 0; nt < 8; nt++)
#pragma unroll
            for (int r = 0; r < 4; r++) s[nt][r] = 0.0f;

#pragma unroll
        for (int g = 0; g < 4; g++) {
            const int bc = 32 * g;
#pragma unroll
            for (int np = 0; np < 4; np++) {
                uint32_t bf[4];
                LDSM_X4(bf[0], bf[1], bf[2], bf[3],
                        Ks + swz(bRow + np * 16, bc + bColOff));
                mma_f16(s[2 * np][0], s[2 * np][1], s[2 * np][2], s[2 * np][3],
                        qa[g][0], qa[g][1], qa[g][2], qa[g][3], bf[0], bf[1]);
                mma_f16(s[2 * np + 1][0], s[2 * np + 1][1],
                        s[2 * np + 1][2], s[2 * np + 1][3],
                        qa[g][0], qa[g][1], qa[g][2], qa[g][3], bf[2], bf[3]);
            }
        }

        const bool domask = (k0 + 63) > r0g;
#pragma unroll
        for (int nt = 0; nt < 8; nt++) {
            const int c0 = k0 + nt * 8 + tig * 2;
            s[nt][0] *= SCALE2; s[nt][1] *= SCALE2;
            s[nt][2] *= SCALE2; s[nt][3] *= SCALE2;
            if (domask) {
                if (c0 > r0g)         s[nt][0] = -1e30f;
                if (c0 + 1 > r0g)     s[nt][1] = -1e30f;
                if (c0 > r0g + 8)     s[nt][2] = -1e30f;
                if (c0 + 1 > r0g + 8) s[nt][3] = -1e30f;
            }
        }

        float mx0 = -1e30f, mx1 = -1e30f;
#pragma unroll
        for (int nt = 0; nt < 8; nt++) {
            mx0 = fmaxf(mx0, fmaxf(s[nt][0], s[nt][1]));
            mx1 = fmaxf(mx1, fmaxf(s[nt][2], s[nt][3]));
        }
        mx0 = fmaxf(mx0, __shfl_xor_sync(0xffffffffu, mx0, 1));
        mx0 = fmaxf(mx0, __shfl_xor_sync(0xffffffffu, mx0, 2));
        mx1 = fmaxf(mx1, __shfl_xor_sync(0xffffffffu, mx1, 1));
        mx1 = fmaxf(mx1, __shfl_xor_sync(0xffffffffu, mx1, 2));

        const float mn0 = fmaxf(m0v, mx0);
        const float mn1 = fmaxf(m1v, mx1);
        const float al0 = ex2(m0v - mn0);
        const float al1 = ex2(m1v - mn1);
        m0v = mn0; m1v = mn1;

        uint32_t ph[8][2];
        float sum0 = 0.0f, sum1 = 0.0f;
#pragma unroll
        for (int nt = 0; nt < 8; nt++) {
            __half2 h01 = __floats2half2_rn(ex2(s[nt][0] - mn0),
                                            ex2(s[nt][1] - mn0));
            __half2 h23 = __floats2half2_rn(ex2(s[nt][2] - mn1),
                                            ex2(s[nt][3] - mn1));
            ph[nt][0] = h2u(h01);
            ph[nt][1] = h2u(h23);
            float2 f01 = __half22float2(h01);
            float2 f23 = __half22float2(h23);
            sum0 += f01.x + f01.y;
            sum1 += f23.x + f23.y;
        }
        sum0 += __shfl_xor_sync(0xffffffffu, sum0, 1);
        sum0 += __shfl_xor_sync(0xffffffffu, sum0, 2);
        sum1 += __shfl_xor_sync(0xffffffffu, sum1, 1);
        sum1 += __shfl_xor_sync(0xffffffffu, sum1, 2);
        l0 = l0 * al0 + sum0;
        l1 = l1 * al1 + sum1;

        // single-change vs R12: skip O rescale when alpha == 1 for all lanes
        const bool resc = !__all_sync(0xffffffffu,
                                      (al0 == 1.0f) & (al1 == 1.0f));
        if (resc) {
#pragma unroll
            for (int nt = 0; nt < 8; nt++) {
                o[nt][0] *= al0; o[nt][1] *= al0;
                o[nt][2] *= al1; o[nt][3] *= al1;
            }
        }

#pragma unroll
        for (int g = 0; g < 4; g++) {
            const int bc = 32 * g;
#pragma unroll
            for (int np = 0; np < 4; np++) {
                uint32_t bf[4];
                LDSM_X4(bf[0], bf[1], bf[2], bf[3],
                        Vs + swz(bRow + np * 16, bc + bColOff));
                mma_f16(o[2 * np][0], o[2 * np][1], o[2 * np][2], o[2 * np][3],
                        ph[2 * g][0], ph[2 * g][1],
                        ph[2 * g + 1][0], ph[2 * g + 1][1], bf[0], bf[1]);
                mma_f16(o[2 * np + 1][0], o[2 * np + 1][1],
                        o[2 * np + 1][2], o[2 * np + 1][3],
                        ph[2 * g][0], ph[2 * g][1],
                        ph[2 * g + 1][0], ph[2 * g + 1][1], bf[2], bf[3]);
            }
        }
    }
#undef ISSUE_KV

    // write ctx fp16
    const int b = bh >> 4, h = bh & 15;
    const float inv0 = 1.0f / l0;
    const float inv1 = 1.0f / l1;
    const int r1g = r0g + 8;
#pragma unroll
    for (int nt = 0; nt < 8; nt++) {
        const int col = h * HDIM + nt * 8 + tig * 2;
        *(__half2*)(g_CTXh + ((size_t)(b * S_LEN + r0g)) * EMB + col)
            = __floats2half2_rn(o[nt][0] * inv0, o[nt][1] * inv0);
        *(__half2*)(g_CTXh + ((size_t)(b * S_LEN + r1g)) * EMB + col)
            = __floats2half2_rn(o[nt][2] * inv1, o[nt][3] * inv1);
    }
}

// ---------------------------------------------------------------------------
extern "C" void kernel_launch(void* const* d_in, const int* in_sizes, int n_in,
                              void* d_out, int out_size)
{
    const float* x      = (const float*)d_in[0];
    const float* w_attn = (const float*)d_in[1];
    const float* b_attn = (const float*)d_in[2];
    const float* w_proj = (const float*)d_in[3];
    const float* b_proj = (const float*)d_in[4];
    float* out = (float*)d_out;

    cudaFuncSetAttribute(gemm_h<0>, cudaFuncAttributeMaxDynamicSharedMemorySize, GSMEM_BYTES);
    cudaFuncSetAttribute(gemm_h<1>, cudaFuncAttributeMaxDynamicSharedMemorySize, GSMEM_BYTES);
    cudaFuncSetAttribute(flash_h,   cudaFuncAttributeMaxDynamicSharedMemorySize, FLASH_SMEM);

    // 0) fused prep: x->fp16 + both weight transposes
    prep_all<<<PREP_BLOCKS, 256>>>(x, w_attn, w_proj);

    // 1) QKV GEMM (persistent, 768 tiles over 296 CTAs)
    gemm_h<0><<<GRID_PERSIST, 256, GSMEM_BYTES>>>(b_attn, nullptr);

    // 2) causal flash attention -> g_CTXh
    flash_h<<<dim3(S_LEN / 128, B_SZ * NHEAD), 256, FLASH_SMEM>>>();

    // 3) projection GEMM (256 tiles < 296 slots, single wave)
    gemm_h<1><<<256, 256, GSMEM_BYTES>>>(b_proj, out);
}

// round 15
// speedup vs baseline: 1.0394x; 1.0155x over previous
#include <cuda_runtime.h>
#include <cuda_fp16.h>
#include <cstdint>
#include <math.h>

// Problem constants
#define B_SZ   2
#define S_LEN  2048
#define EMB    1024
#define NHEAD  16
#define HDIM   64
#define ROWS   (B_SZ * S_LEN)          // 4096

// Scratch (device globals -> no allocation). All fp16 operand tensors.
__device__ __half g_Qh [B_SZ * NHEAD * S_LEN * HDIM];   // [b,h,s,d]
__device__ __half g_Kh [B_SZ * NHEAD * S_LEN * HDIM];   // [b,h,s,d]
__device__ __half g_Vh [B_SZ * NHEAD * S_LEN * HDIM];   // [b,h,s,d] (natural!)
__device__ __half g_CTXh[ROWS * EMB];
__device__ __half g_Xh  [ROWS * EMB];
__device__ __half g_WaTh[3 * EMB * EMB];                // w_attn^T [3072][1024]
__device__ __half g_WpTh[EMB * EMB];                    // w_proj^T [1024][1024]

// ---------------------------------------------------------------------------
// Helpers
// ---------------------------------------------------------------------------
__device__ __forceinline__ uint32_t smem_u32(const void* p) {
    uint32_t a;
    asm("{ .reg .u64 t; cvta.to.shared.u64 t, %1; cvt.u32.u64 %0, t; }"
        : "=r"(a) : "l"(p));
    return a;
}
__device__ __forceinline__ void cp16(uint32_t smaddr, const void* gaddr) {
    asm volatile("cp.async.cg.shared.global [%0], [%1], 16;"
                 :: "r"(smaddr), "l"(gaddr) : "memory");
}
__device__ __forceinline__ uint32_t h2u(__half2 h) {
    return *reinterpret_cast<uint32_t*>(&h);
}
__device__ __forceinline__ float ex2(float x) {
    float y;
    asm("ex2.approx.ftz.f32 %0, %1;" : "=f"(y) : "f"(x));
    return y;
}
__device__ __forceinline__ void mma_f16(float& d0, float& d1, float& d2, float& d3,
                                        uint32_t a0, uint32_t a1, uint32_t a2, uint32_t a3,
                                        uint32_t b0, uint32_t b1) {
    asm volatile(
        "mma.sync.aligned.m16n8k16.row.col.f32.f16.f16.f32 "
        "{%0,%1,%2,%3},{%4,%5,%6,%7},{%8,%9},{%0,%1,%2,%3};"
        : "+f"(d0), "+f"(d1), "+f"(d2), "+f"(d3)
        : "r"(a0), "r"(a1), "r"(a2), "r"(a3), "r"(b0), "r"(b1));
}
#define LDSM_X4(r0, r1, r2, r3, addr)                                          \
    asm volatile("ldmatrix.sync.aligned.m8n8.x4.shared.b16 {%0,%1,%2,%3}, [%4];" \
                 : "=r"(r0), "=r"(r1), "=r"(r2), "=r"(r3) : "r"(addr))
#define LDSM_X4_T(r0, r1, r2, r3, addr)                                        \
    asm volatile("ldmatrix.sync.aligned.m8n8.x4.trans.shared.b16 {%0,%1,%2,%3}, [%4];" \
                 : "=r"(r0), "=r"(r1), "=r"(r2), "=r"(r3) : "r"(addr))

// XOR swizzle within a 128B row: 16B chunk index ^ (row & 7)
__device__ __forceinline__ uint32_t swz(int row, int bc) {
    return (uint32_t)(row * 128 + (((bc >> 4) ^ (row & 7)) << 4) + (bc & 15));
}

// ---------------------------------------------------------------------------
// Fused prep: x -> fp16 copy, plus both weight transposes (fp32->fp16).
// ---------------------------------------------------------------------------
#define PREP_CVT_BLOCKS 4096
#define PREP_WA_BLOCKS  3072
#define PREP_WP_BLOCKS  1024
#define PREP_BLOCKS (PREP_CVT_BLOCKS + PREP_WA_BLOCKS + PREP_WP_BLOCKS)

__global__ void prep_all(const float* __restrict__ x,
                         const float* __restrict__ w_attn,
                         const float* __restrict__ w_proj)
{
    const int bid = blockIdx.x;
    if (bid < PREP_CVT_BLOCKS) {
        int i = (bid * 256 + threadIdx.x) * 4;
        float4 v = *(const float4*)(x + i);
        __half2* o = (__half2*)(g_Xh + i);
        o[0] = __floats2half2_rn(v.x, v.y);
        o[1] = __floats2half2_rn(v.z, v.w);
        return;
    }
    __shared__ float t[32][33];
    const float* src;
    __half* dst;
    int N, nblk_x, tb;
    if (bid < PREP_CVT_BLOCKS + PREP_WA_BLOCKS) {
        tb = bid - PREP_CVT_BLOCKS;
        src = w_attn; dst = g_WaTh; N = 3 * EMB; nblk_x = (3 * EMB) / 32;
    } else {
        tb = bid - PREP_CVT_BLOCKS - PREP_WA_BLOCKS;
        src = w_proj; dst = g_WpTh; N = EMB; nblk_x = EMB / 32;
    }
    const int K = EMB;
    const int x_ = threadIdx.x & 31, y_ = threadIdx.x >> 5;
    const int n0 = (tb % nblk_x) * 32, k0 = (tb / nblk_x) * 32;
#pragma unroll
    for (int i = 0; i < 4; i++)
        t[y_ + i * 8][x_] = src[(size_t)(k0 + y_ + i * 8) * N + n0 + x_];
    __syncthreads();
#pragma unroll
    for (int i = 0; i < 4; i++)
        dst[(size_t)(n0 + y_ + i * 8) * K + k0 + x_] = __float2half_rn(t[x_][y_ + i * 8]);
}

// ---------------------------------------------------------------------------
// fp16 mma.sync GEMM (R10/R12-proven) + persistent grid-stride tiles.
// CTA 128x128, 8 warps (2x4, warp 64x32), TK=64, 3-stage cp.async.
// All of Q/K/V now written coalesced [b,h,s,d] (no transposed scatter).
// ---------------------------------------------------------------------------
#define CMM 128
#define CNN 128
#define TKK 64
#define A_BY (CMM * TKK * 2)            // 16384
#define STG_B (2 * A_BY)                // 32768
#define SPIPE 3
#define GSMEM_BYTES (SPIPE * STG_B)     // 98304
#define NSTAGE (EMB / TKK)              // 16
#define GRID_PERSIST 296                // 148 SMs * 2 CTA

template <int MODE>
__global__ void __launch_bounds__(256, 2)
gemm_h(const float* __restrict__ bias, float* __restrict__ Cout)
{
    extern __shared__ char smc[];
    const uint32_t sb = smem_u32(smc);
    const int tid  = threadIdx.x;
    const int wid  = tid >> 5;
    const int lane = tid & 31;
    const int gid  = lane >> 2;
    const int tig  = lane & 3;
    const int warp_m = (wid >> 2) * 64;
    const int warp_n = (wid & 3) * 32;

    const __half* A  = (MODE == 1) ? g_CTXh : g_Xh;
    const __half* BT = (MODE == 1) ? g_WpTh : g_WaTh;

    const int NX = (MODE == 1) ? 8 : 24;
    const int NT = (MODE == 1) ? 256 : 768;

    const int lsel  = lane >> 3;
    const int lrow8 = lane & 7;
    const int aRowL   = warp_m + ((lsel & 1) << 3) + lrow8;
    const int aColOff = (lsel >> 1) << 4;
    const int bRowL   = warp_n + ((lsel >> 1) << 3) + lrow8;
    const int bColOff = (lsel & 1) << 4;

    const int lrow = tid >> 1;
    const int cb   = (tid & 1) * 4;

    for (int t = blockIdx.x; t < NT; t += gridDim.x) {
        const int m0 = (t / NX) * CMM;
        const int n0 = (t % NX) * CNN;

        float acc[4][4][4];
#pragma unroll
        for (int mt = 0; mt < 4; mt++)
#pragma unroll
            for (int nt = 0; nt < 4; nt++)
#pragma unroll
                for (int r = 0; r < 4; r++) acc[mt][nt][r] = 0.0f;

        const __half* gA = A  + (size_t)(m0 + lrow) * EMB;
        const __half* gB = BT + (size_t)(n0 + lrow) * EMB;

#define ISSUE(s_)                                                              \
        {                                                                      \
            uint32_t st = sb + (uint32_t)(((s_) % SPIPE) * STG_B);             \
            const __half* ga = gA + (s_) * TKK;                                \
            const __half* gb = gB + (s_) * TKK;                                \
            _Pragma("unroll")                                                  \
            for (int c = 0; c < 4; c++) {                                      \
                cp16(st + swz(lrow, (cb + c) * 16), ga + (cb + c) * 8);        \
                cp16(st + A_BY + swz(lrow, (cb + c) * 16), gb + (cb + c) * 8); \
            }                                                                  \
        }

        ISSUE(0); asm volatile("cp.async.commit_group;" ::: "memory");
        ISSUE(1); asm volatile("cp.async.commit_group;" ::: "memory");
        asm volatile("cp.async.wait_group 1;" ::: "memory");
        __syncthreads();

        for (int s = 0; s < NSTAGE; s++) {
            if (s + 2 < NSTAGE) ISSUE(s + 2);
            asm volatile("cp.async.commit_group;" ::: "memory");

            const uint32_t stA = sb + (uint32_t)((s % SPIPE) * STG_B);
            const uint32_t stB = stA + A_BY;
#pragma unroll
            for (int g = 0; g < 4; g++) {
                const int bc = 32 * g;
                uint32_t af[4][4], bf[2][4];
#pragma unroll
                for (int mt = 0; mt < 4; mt++)
                    LDSM_X4(af[mt][0], af[mt][1], af[mt][2], af[mt][3],
                            stA + swz(aRowL + mt * 16, bc + aColOff));
#pragma unroll
                for (int np = 0; np < 2; np++)
                    LDSM_X4(bf[np][0], bf[np][1], bf[np][2], bf[np][3],
                            stB + swz(bRowL + np * 16, bc + bColOff));
#pragma unroll
                for (int mt = 0; mt < 4; mt++)
#pragma unroll
                    for (int nt = 0; nt < 4; nt++)
                        mma_f16(acc[mt][nt][0], acc[mt][nt][1],
                                acc[mt][nt][2], acc[mt][nt][3],
                                af[mt][0], af[mt][1], af[mt][2], af[mt][3],
                                bf[nt >> 1][(nt & 1) * 2], bf[nt >> 1][(nt & 1) * 2 + 1]);
            }
            asm volatile("cp.async.wait_group 1;" ::: "memory");
            __syncthreads();
        }
#undef ISSUE

#pragma unroll
        for (int mt = 0; mt < 4; mt++) {
            const int r0 = m0 + warp_m + mt * 16 + gid;
            const int r1 = r0 + 8;
#pragma unroll
            for (int nt = 0; nt < 4; nt++) {
                const int nb = n0 + warp_n + nt * 8;
                const int c  = nb + tig * 2;
                const float2 bv = *(const float2*)(bias + c);
                float2 o0, o1;
                o0.x = acc[mt][nt][0] + bv.x;
                o0.y = acc[mt][nt][1] + bv.y;
                o1.x = acc[mt][nt][2] + bv.x;
                o1.y = acc[mt][nt][3] + bv.y;
                if (MODE == 1) {
                    *(float2*)(Cout + (size_t)r0 * EMB + c) = o0;
                    *(float2*)(Cout + (size_t)r1 * EMB + c) = o1;
                } else {
                    const int which = nb >> 10;
                    const int e  = nb & 1023;
                    const int h  = e >> 6;
                    const int dd = (e & 63) + tig * 2;
                    const int b0i = r0 >> 11, s0i = r0 & 2047;
                    const int b1i = r1 >> 11, s1i = r1 & 2047;
                    __half* dst = (which == 0) ? g_Qh : (which == 1) ? g_Kh : g_Vh;
                    *(__half2*)(dst + ((size_t)(b0i * NHEAD + h) * S_LEN + s0i) * HDIM + dd)
                        = __floats2half2_rn(o0.x, o0.y);
                    *(__half2*)(dst + ((size_t)(b1i * NHEAD + h) * S_LEN + s1i) * HDIM + dd)
                        = __floats2half2_rn(o1.x, o1.y);
                }
            }
        }
    }
}

// ---------------------------------------------------------------------------
// Flash attention (causal), fp16 mma + ldmatrix. Base-2 softmax (raw MUFU).
// CTA 256 thr / 8 warps, q-tile 128, k-tile 64, D=64. K/V triple-buffered.
// V stored natural [s][d]; P*V B-fragments via ldmatrix.trans.
// ---------------------------------------------------------------------------
#define FQ_BY (128 * 128)               // Q tile 16KB
#define FK_BY (64 * 128)                // 8KB per K/V buffer
#define KOFF  FQ_BY
#define VOFF  (FQ_BY + 3 * FK_BY)
#define FLASH_SMEM (FQ_BY + 6 * FK_BY)  // 65536

#define SCALE2 0.18033688011112042f     // 0.125 * log2(e)

__global__ void __launch_bounds__(256, 2)
flash_h()
{
    extern __shared__ char smc[];
    const uint32_t sb = smem_u32(smc);
    const int tid  = threadIdx.x;
    const int wid  = tid >> 5;
    const int lane = tid & 31;
    const int gid  = lane >> 2;
    const int tig  = lane & 3;
    const int qt   = gridDim.x - 1 - blockIdx.x;   // heavy tiles first
    const int bh   = blockIdx.y;
    const int q0   = qt * 128;

    const __half* Qg = g_Qh + (size_t)bh * S_LEN * HDIM;
    const __half* Kg = g_Kh + (size_t)bh * S_LEN * HDIM;
    const __half* Vg = g_Vh + (size_t)bh * S_LEN * HDIM;

    const int lsel  = lane >> 3;
    const int lrow8 = lane & 7;
    const int aRow    = wid * 16 + ((lsel & 1) << 3) + lrow8;
    const int aColOff = (lsel >> 1) << 4;
    const int bRow    = ((lsel >> 1) << 3) + lrow8;
    const int bColOff = (lsel & 1) << 4;
    // V trans-fragment octet map (A-style): key-row + d-byte
    const int vRow    = ((lsel & 1) << 3) + lrow8;
    const int vColOff = (lsel >> 1) << 4;

    // Q load
    {
        const int r = tid >> 1, c0 = (tid & 1) * 4;
        const __half* gq = Qg + (size_t)(q0 + r) * HDIM;
#pragma unroll
        for (int c = 0; c < 4; c++)
            cp16(sb + swz(r, (c0 + c) * 16), gq + (c0 + c) * 8);
    }

#define ISSUE_KV(kt_)                                                          \
    {                                                                          \
        const int buf_ = (kt_) % 3;                                            \
        const int r = tid >> 2, c0 = (tid & 3) * 2;                            \
        const __half* gk = Kg + (size_t)((kt_) * 64 + r) * HDIM;               \
        const __half* gv = Vg + (size_t)((kt_) * 64 + r) * HDIM;               \
        _Pragma("unroll")                                                      \
        for (int c = 0; c < 2; c++) {                                          \
            cp16(sb + KOFF + buf_ * FK_BY + swz(r, (c0 + c) * 16),             \
                 gk + (c0 + c) * 8);                                           \
            cp16(sb + VOFF + buf_ * FK_BY + swz(r, (c0 + c) * 16),             \
                 gv + (c0 + c) * 8);                                           \
        }                                                                      \
    }

    const int nkt = 2 * (qt + 1);

    ISSUE_KV(0);
    asm volatile("cp.async.commit_group;" ::: "memory");
    if (nkt > 1) ISSUE_KV(1);
    asm volatile("cp.async.commit_group;" ::: "memory");
    asm volatile("cp.async.wait_group 1;" ::: "memory");
    __syncthreads();

    uint32_t qa[4][4];
#pragma unroll
    for (int g = 0; g < 4; g++)
        LDSM_X4(qa[g][0], qa[g][1], qa[g][2], qa[g][3],
                sb + swz(aRow, 32 * g + aColOff));

    float m0v = -1e30f, m1v = -1e30f, l0 = 0.0f, l1 = 0.0f;
    float o[8][4];
#pragma unroll
    for (int nt = 0; nt < 8; nt++)
#pragma unroll
        for (int r = 0; r < 4; r++) o[nt][r] = 0.0f;

    const int r0g = q0 + wid * 16 + gid;

    for (int kt = 0; kt < nkt; kt++) {
        if (kt > 0) {
            asm volatile("cp.async.wait_group 1;" ::: "memory");
            __syncthreads();
        }
        if (kt + 2 < nkt) ISSUE_KV(kt + 2);
        asm volatile("cp.async.commit_group;" ::: "memory");

        const uint32_t Ks = sb + KOFF + (uint32_t)((kt % 3) * FK_BY);
        const uint32_t Vs = sb + VOFF + (uint32_t)((kt % 3) * FK_BY);
        const int k0 = kt * 64;

        float s[8][4];
#pragma unroll
        for (int nt = 0; nt < 8; nt++)
#pragma unroll
            for (int r = 0; r < 4; r++) s[nt][r] = 0.0f;

#pragma unroll
        for (int g = 0; g < 4; g++) {
            const int bc = 32 * g;
#pragma unroll
            for (int np = 0; np < 4; np++) {
                uint32_t bf[4];
                LDSM_X4(bf[0], bf[1], bf[2], bf[3],
                        Ks + swz(bRow + np * 16, bc + bColOff));
                mma_f16(s[2 * np][0], s[2 * np][1], s[2 * np][2], s[2 * np][3],
                        qa[g][0], qa[g][1], qa[g][2], qa[g][3], bf[0], bf[1]);
                mma_f16(s[2 * np + 1][0], s[2 * np + 1][1],
                        s[2 * np + 1][2], s[2 * np + 1][3],
                        qa[g][0], qa[g][1], qa[g][2], qa[g][3], bf[2], bf[3]);
            }
        }

        const bool domask = (k0 + 63) > r0g;
#pragma unroll
        for (int nt = 0; nt < 8; nt++) {
            const int c0 = k0 + nt * 8 + tig * 2;
            s[nt][0] *= SCALE2; s[nt][1] *= SCALE2;
            s[nt][2] *= SCALE2; s[nt][3] *= SCALE2;
            if (domask) {
                if (c0 > r0g)         s[nt][0] = -1e30f;
                if (c0 + 1 > r0g)     s[nt][1] = -1e30f;
                if (c0 > r0g + 8)     s[nt][2] = -1e30f;
                if (c0 + 1 > r0g + 8) s[nt][3] = -1e30f;
            }
        }

        float mx0 = -1e30f, mx1 = -1e30f;
#pragma unroll
        for (int nt = 0; nt < 8; nt++) {
            mx0 = fmaxf(mx0, fmaxf(s[nt][0], s[nt][1]));
            mx1 = fmaxf(mx1, fmaxf(s[nt][2], s[nt][3]));
        }
        mx0 = fmaxf(mx0, __shfl_xor_sync(0xffffffffu, mx0, 1));
        mx0 = fmaxf(mx0, __shfl_xor_sync(0xffffffffu, mx0, 2));
        mx1 = fmaxf(mx1, __shfl_xor_sync(0xffffffffu, mx1, 1));
        mx1 = fmaxf(mx1, __shfl_xor_sync(0xffffffffu, mx1, 2));

        const float mn0 = fmaxf(m0v, mx0);
        const float mn1 = fmaxf(m1v, mx1);
        const float al0 = ex2(m0v - mn0);
        const float al1 = ex2(m1v - mn1);
        m0v = mn0; m1v = mn1;

        uint32_t ph[8][2];
        float sum0 = 0.0f, sum1 = 0.0f;
#pragma unroll
        for (int nt = 0; nt < 8; nt++) {
            __half2 h01 = __floats2half2_rn(ex2(s[nt][0] - mn0),
                                            ex2(s[nt][1] - mn0));
            __half2 h23 = __floats2half2_rn(ex2(s[nt][2] - mn1),
                                            ex2(s[nt][3] - mn1));
            ph[nt][0] = h2u(h01);
            ph[nt][1] = h2u(h23);
            float2 f01 = __half22float2(h01);
            float2 f23 = __half22float2(h23);
            sum0 += f01.x + f01.y;
            sum1 += f23.x + f23.y;
        }
        sum0 += __shfl_xor_sync(0xffffffffu, sum0, 1);
        sum0 += __shfl_xor_sync(0xffffffffu, sum0, 2);
        sum1 += __shfl_xor_sync(0xffffffffu, sum1, 1);
        sum1 += __shfl_xor_sync(0xffffffffu, sum1, 2);
        l0 = l0 * al0 + sum0;
        l1 = l1 * al1 + sum1;

#pragma unroll
        for (int nt = 0; nt < 8; nt++) {
            o[nt][0] *= al0; o[nt][1] *= al0;
            o[nt][2] *= al1; o[nt][3] *= al1;
        }

        // O += P V : B-fragments from natural-layout V via ldmatrix.trans.
        // Source blocks: keys 16g + vRow, d bytes np*32 + vColOff.
#pragma unroll
        for (int g = 0; g < 4; g++) {
#pragma unroll
            for (int np = 0; np < 4; np++) {
                uint32_t bf[4];
                LDSM_X4_T(bf[0], bf[1], bf[2], bf[3],
                          Vs + swz(16 * g + vRow, np * 32 + vColOff));
                mma_f16(o[2 * np][0], o[2 * np][1], o[2 * np][2], o[2 * np][3],
                        ph[2 * g][0], ph[2 * g][1],
                        ph[2 * g + 1][0], ph[2 * g + 1][1], bf[0], bf[1]);
                mma_f16(o[2 * np + 1][0], o[2 * np + 1][1],
                        o[2 * np + 1][2], o[2 * np + 1][3],
                        ph[2 * g][0], ph[2 * g][1],
                        ph[2 * g + 1][0], ph[2 * g + 1][1], bf[2], bf[3]);
            }
        }
    }
#undef ISSUE_KV

    // write ctx fp16
    const int b = bh >> 4, h = bh & 15;
    const float inv0 = 1.0f / l0;
    const float inv1 = 1.0f / l1;
    const int r1g = r0g + 8;
#pragma unroll
    for (int nt = 0; nt < 8; nt++) {
        const int col = h * HDIM + nt * 8 + tig * 2;
        *(__half2*)(g_CTXh + ((size_t)(b * S_LEN + r0g)) * EMB + col)
            = __floats2half2_rn(o[nt][0] * inv0, o[nt][1] * inv0);
        *(__half2*)(g_CTXh + ((size_t)(b * S_LEN + r1g)) * EMB + col)
            = __floats2half2_rn(o[nt][2] * inv1, o[nt][3] * inv1);
    }
}

// ---------------------------------------------------------------------------
extern "C" void kernel_launch(void* const* d_in, const int* in_sizes, int n_in,
                              void* d_out, int out_size)
{
    const float* x      = (const float*)d_in[0];
    const float* w_attn = (const float*)d_in[1];
    const float* b_attn = (const float*)d_in[2];
    const float* w_proj = (const float*)d_in[3];
    const float* b_proj = (const float*)d_in[4];
    float* out = (float*)d_out;

    cudaFuncSetAttribute(gemm_h<0>, cudaFuncAttributeMaxDynamicSharedMemorySize, GSMEM_BYTES);
    cudaFuncSetAttribute(gemm_h<1>, cudaFuncAttributeMaxDynamicSharedMemorySize, GSMEM_BYTES);
    cudaFuncSetAttribute(flash_h,   cudaFuncAttributeMaxDynamicSharedMemorySize, FLASH_SMEM);

    // 0) fused prep: x->fp16 + both weight transposes
    prep_all<<<PREP_BLOCKS, 256>>>(x, w_attn, w_proj);

    // 1) QKV GEMM (persistent, 768 tiles over 296 CTAs)
    gemm_h<0><<<GRID_PERSIST, 256, GSMEM_BYTES>>>(b_attn, nullptr);

    // 2) causal flash attention -> g_CTXh
    flash_h<<<dim3(S_LEN / 128, B_SZ * NHEAD), 256, FLASH_SMEM>>>();

    // 3) projection GEMM (256 tiles < 296 slots, single wave)
    gemm_h<1><<<256, 256, GSMEM_BYTES>>>(b_proj, out);
}

// round 16
// speedup vs baseline: 1.1314x; 1.0885x over previous
#include <cuda_runtime.h>
#include <cuda_fp16.h>
#include <cstdint>
#include <math.h>

// Problem constants
#define B_SZ   2
#define S_LEN  2048
#define EMB    1024
#define NHEAD  16
#define HDIM   64
#define ROWS   (B_SZ * S_LEN)          // 4096

// Scratch (device globals -> no allocation). All fp16 operand tensors.
__device__ __half g_Qh [B_SZ * NHEAD * S_LEN * HDIM];   // [b,h,s,d], PRE-SCALED by SCALE2
__device__ __half g_Kh [B_SZ * NHEAD * S_LEN * HDIM];   // [b,h,s,d]
__device__ __half g_Vh [B_SZ * NHEAD * S_LEN * HDIM];   // [b,h,s,d]
__device__ __half g_CTXh[ROWS * EMB];
__device__ __half g_Xh  [ROWS * EMB];
__device__ __half g_WaTh[3 * EMB * EMB];                // w_attn^T [3072][1024]
__device__ __half g_WpTh[EMB * EMB];                    // w_proj^T [1024][1024]
__device__ int    g_ctr[32];            // per-128-row ctx tile: heads completed

#define SCALE2 0.18033688011112042f     // 0.125 * log2(e)

// ---------------------------------------------------------------------------
// Helpers
// ---------------------------------------------------------------------------
__device__ __forceinline__ uint32_t smem_u32(const void* p) {
    uint32_t a;
    asm("{ .reg .u64 t; cvta.to.shared.u64 t, %1; cvt.u32.u64 %0, t; }"
        : "=r"(a) : "l"(p));
    return a;
}
__device__ __forceinline__ void cp16(uint32_t smaddr, const void* gaddr) {
    asm volatile("cp.async.cg.shared.global [%0], [%1], 16;"
                 :: "r"(smaddr), "l"(gaddr) : "memory");
}
__device__ __forceinline__ uint32_t h2u(__half2 h) {
    return *reinterpret_cast<uint32_t*>(&h);
}
__device__ __forceinline__ float ex2(float x) {
    float y;
    asm("ex2.approx.ftz.f32 %0, %1;" : "=f"(y) : "f"(x));
    return y;
}
__device__ __forceinline__ void mma_f16(float& d0, float& d1, float& d2, float& d3,
                                        uint32_t a0, uint32_t a1, uint32_t a2, uint32_t a3,
                                        uint32_t b0, uint32_t b1) {
    asm volatile(
        "mma.sync.aligned.m16n8k16.row.col.f32.f16.f16.f32 "
        "{%0,%1,%2,%3},{%4,%5,%6,%7},{%8,%9},{%0,%1,%2,%3};"
        : "+f"(d0), "+f"(d1), "+f"(d2), "+f"(d3)
        : "r"(a0), "r"(a1), "r"(a2), "r"(a3), "r"(b0), "r"(b1));
}
#define LDSM_X4(r0, r1, r2, r3, addr)                                          \
    asm volatile("ldmatrix.sync.aligned.m8n8.x4.shared.b16 {%0,%1,%2,%3}, [%4];" \
                 : "=r"(r0), "=r"(r1), "=r"(r2), "=r"(r3) : "r"(addr))
#define LDSM_X4_T(r0, r1, r2, r3, addr)                                        \
    asm volatile("ldmatrix.sync.aligned.m8n8.x4.trans.shared.b16 {%0,%1,%2,%3}, [%4];" \
                 : "=r"(r0), "=r"(r1), "=r"(r2), "=r"(r3) : "r"(addr))

__device__ __forceinline__ uint32_t swz(int row, int bc) {
    return (uint32_t)(row * 128 + (((bc >> 4) ^ (row & 7)) << 4) + (bc & 15));
}

// ---------------------------------------------------------------------------
// Fused prep: x -> fp16, weight transposes, counter reset.
// ---------------------------------------------------------------------------
#define PREP_CVT_BLOCKS 4096
#define PREP_WA_BLOCKS  3072
#define PREP_WP_BLOCKS  1024
#define PREP_BLOCKS (PREP_CVT_BLOCKS + PREP_WA_BLOCKS + PREP_WP_BLOCKS)

__global__ void prep_all(const float* __restrict__ x,
                         const float* __restrict__ w_attn,
                         const float* __restrict__ w_proj)
{
    const int bid = blockIdx.x;
    if (bid == 0 && threadIdx.x < 32) g_ctr[threadIdx.x] = 0;
    if (bid < PREP_CVT_BLOCKS) {
        int i = (bid * 256 + threadIdx.x) * 4;
        float4 v = *(const float4*)(x + i);
        __half2* o = (__half2*)(g_Xh + i);
        o[0] = __floats2half2_rn(v.x, v.y);
        o[1] = __floats2half2_rn(v.z, v.w);
        return;
    }
    __shared__ float t[32][33];
    const float* src;
    __half* dst;
    int N, nblk_x, tb;
    if (bid < PREP_CVT_BLOCKS + PREP_WA_BLOCKS) {
        tb = bid - PREP_CVT_BLOCKS;
        src = w_attn; dst = g_WaTh; N = 3 * EMB; nblk_x = (3 * EMB) / 32;
    } else {
        tb = bid - PREP_CVT_BLOCKS - PREP_WA_BLOCKS;
        src = w_proj; dst = g_WpTh; N = EMB; nblk_x = EMB / 32;
    }
    const int K = EMB;
    const int x_ = threadIdx.x & 31, y_ = threadIdx.x >> 5;
    const int n0 = (tb % nblk_x) * 32, k0 = (tb / nblk_x) * 32;
#pragma unroll
    for (int i = 0; i < 4; i++)
        t[y_ + i * 8][x_] = src[(size_t)(k0 + y_ + i * 8) * N + n0 + x_];
    __syncthreads();
#pragma unroll
    for (int i = 0; i < 4; i++)
        dst[(size_t)(n0 + y_ + i * 8) * K + k0 + x_] = __float2half_rn(t[x_][y_ + i * 8]);
}

// ---------------------------------------------------------------------------
// GEMM tiling constants (shared by gemm0 and proj role)
// ---------------------------------------------------------------------------
#define CMM 128
#define CNN 128
#define TKK 64
#define A_BY (CMM * TKK * 2)            // 16384
#define STG_B (2 * A_BY)                // 32768
#define SPIPE 3
#define GSMEM_BYTES (SPIPE * STG_B)     // 98304
#define NSTAGE (EMB / TKK)              // 16
#define GRID_PERSIST 296                // 148 SMs * 2 CTA

// GEMM mainloop+epilogue as a device function operating on the caller's smem.
// MODE 0: A=g_Xh, BT=g_WaTh -> Q(pre-scaled)/K/V fp16 [b,h,s,d]
// MODE 1: A=g_CTXh, BT=g_WpTh -> Cout fp32
template <int MODE>
__device__ __forceinline__ void gemm_tile_body(
    const uint32_t sb, char* smc, int m0, int n0,
    const float* __restrict__ bias, float* __restrict__ Cout)
{
    const int tid  = threadIdx.x;
    const int wid  = tid >> 5;
    const int lane = tid & 31;
    const int gid  = lane >> 2;
    const int tig  = lane & 3;
    const int warp_m = (wid >> 2) * 64;
    const int warp_n = (wid & 3) * 32;

    const __half* A  = (MODE == 1) ? g_CTXh : g_Xh;
    const __half* BT = (MODE == 1) ? g_WpTh : g_WaTh;

    const int lsel  = lane >> 3;
    const int lrow8 = lane & 7;
    const int aRowL   = warp_m + ((lsel & 1) << 3) + lrow8;
    const int aColOff = (lsel >> 1) << 4;
    const int bRowL   = warp_n + ((lsel >> 1) << 3) + lrow8;
    const int bColOff = (lsel & 1) << 4;

    const int lrow = tid >> 1;
    const int cb   = (tid & 1) * 4;

    float acc[4][4][4];
#pragma unroll
    for (int mt = 0; mt < 4; mt++)
#pragma unroll
        for (int nt = 0; nt < 4; nt++)
#pragma unroll
            for (int r = 0; r < 4; r++) acc[mt][nt][r] = 0.0f;

    const __half* gA = A  + (size_t)(m0 + lrow) * EMB;
    const __half* gB = BT + (size_t)(n0 + lrow) * EMB;

#define ISSUE(s_)                                                              \
    {                                                                          \
        uint32_t st = sb + (uint32_t)(((s_) % SPIPE) * STG_B);                 \
        const __half* ga = gA + (s_) * TKK;                                    \
        const __half* gb = gB + (s_) * TKK;                                    \
        _Pragma("unroll")                                                      \
        for (int c = 0; c < 4; c++) {                                          \
            cp16(st + swz(lrow, (cb + c) * 16), ga + (cb + c) * 8);            \
            cp16(st + A_BY + swz(lrow, (cb + c) * 16), gb + (cb + c) * 8);     \
        }                                                                      \
    }

    ISSUE(0); asm volatile("cp.async.commit_group;" ::: "memory");
    ISSUE(1); asm volatile("cp.async.commit_group;" ::: "memory");
    asm volatile("cp.async.wait_group 1;" ::: "memory");
    __syncthreads();

    for (int s = 0; s < NSTAGE; s++) {
        if (s + 2 < NSTAGE) ISSUE(s + 2);
        asm volatile("cp.async.commit_group;" ::: "memory");

        const uint32_t stA = sb + (uint32_t)((s % SPIPE) * STG_B);
        const uint32_t stB = stA + A_BY;
#pragma unroll
        for (int g = 0; g < 4; g++) {
            const int bc = 32 * g;
            uint32_t af[4][4], bf[2][4];
#pragma unroll
            for (int mt = 0; mt < 4; mt++)
                LDSM_X4(af[mt][0], af[mt][1], af[mt][2], af[mt][3],
                        stA + swz(aRowL + mt * 16, bc + aColOff));
#pragma unroll
            for (int np = 0; np < 2; np++)
                LDSM_X4(bf[np][0], bf[np][1], bf[np][2], bf[np][3],
                        stB + swz(bRowL + np * 16, bc + bColOff));
#pragma unroll
            for (int mt = 0; mt < 4; mt++)
#pragma unroll
                for (int nt = 0; nt < 4; nt++)
                    mma_f16(acc[mt][nt][0], acc[mt][nt][1],
                            acc[mt][nt][2], acc[mt][nt][3],
                            af[mt][0], af[mt][1], af[mt][2], af[mt][3],
                            bf[nt >> 1][(nt & 1) * 2], bf[nt >> 1][(nt & 1) * 2 + 1]);
        }
        asm volatile("cp.async.wait_group 1;" ::: "memory");
        __syncthreads();
    }
#undef ISSUE

#pragma unroll
    for (int mt = 0; mt < 4; mt++) {
        const int r0 = m0 + warp_m + mt * 16 + gid;
        const int r1 = r0 + 8;
#pragma unroll
        for (int nt = 0; nt < 4; nt++) {
            const int nb = n0 + warp_n + nt * 8;
            const int c  = nb + tig * 2;
            const float2 bv = *(const float2*)(bias + c);
            float2 o0, o1;
            o0.x = acc[mt][nt][0] + bv.x;
            o0.y = acc[mt][nt][1] + bv.y;
            o1.x = acc[mt][nt][2] + bv.x;
            o1.y = acc[mt][nt][3] + bv.y;
            if (MODE == 1) {
                *(float2*)(Cout + (size_t)r0 * EMB + c) = o0;
                *(float2*)(Cout + (size_t)r1 * EMB + c) = o1;
            } else {
                const int which = nb >> 10;
                const int e  = nb & 1023;
                const int h  = e >> 6;
                const int dd = (e & 63) + tig * 2;
                const int b0i = r0 >> 11, s0i = r0 & 2047;
                const int b1i = r1 >> 11, s1i = r1 & 2047;
                if (which == 0) {       // Q pre-scaled by SCALE2
                    o0.x *= SCALE2; o0.y *= SCALE2;
                    o1.x *= SCALE2; o1.y *= SCALE2;
                }
                __half* dst = (which == 0) ? g_Qh : (which == 1) ? g_Kh : g_Vh;
                *(__half2*)(dst + ((size_t)(b0i * NHEAD + h) * S_LEN + s0i) * HDIM + dd)
                    = __floats2half2_rn(o0.x, o0.y);
                *(__half2*)(dst + ((size_t)(b1i * NHEAD + h) * S_LEN + s1i) * HDIM + dd)
                    = __floats2half2_rn(o1.x, o1.y);
            }
        }
    }
}

// QKV GEMM: persistent grid-stride over 768 tiles.
__global__ void __launch_bounds__(256, 2)
gemm_qkv(const float* __restrict__ bias)
{
    extern __shared__ char smc[];
    const uint32_t sb = smem_u32(smc);
    for (int t = blockIdx.x; t < 768; t += gridDim.x) {
        gemm_tile_body<0>(sb, smc, (t / 24) * CMM, (t % 24) * CNN, bias, nullptr);
    }
}

// ---------------------------------------------------------------------------
// Fused flash attention + projection GEMM.
// bids [0,512): flash role (heavy qt dispatched first), signals g_ctr.
// bids [512,768): proj role, spins on g_ctr[rowtile] == 16 then MODE-1 GEMM.
// ---------------------------------------------------------------------------
#define FQ_BY (128 * 128)
#define FK_BY (64 * 128)
#define KOFF  FQ_BY
#define VOFF  (FQ_BY + 3 * FK_BY)
#define FUSED_SMEM GSMEM_BYTES          // 96KB >= flash's 64KB

__global__ void __launch_bounds__(256, 2)
flash_proj(const float* __restrict__ b_proj, float* __restrict__ out)
{
    extern __shared__ char smc[];
    const uint32_t sb = smem_u32(smc);
    const int bid = blockIdx.x;
    const int tid = threadIdx.x;

    if (bid >= 512) {
        // ------------------- projection role -------------------
        const int t  = bid - 512;            // 0..255
        const int j  = t >> 3;               // 0..31 row-tile order index
        const int n0 = (t & 7) * CNN;
        const int qt_ = 15 - (j >> 1);       // heavy q-tiles first (match producers)
        const int b_  = j & 1;
        const int mtile = b_ * 16 + qt_;
        const int m0 = mtile * CMM;

        if (tid == 0) {
            while (atomicAdd(&g_ctr[mtile], 0) < NHEAD) __nanosleep(200);
        }
        __syncthreads();
        __threadfence();
        gemm_tile_body<1>(sb, smc, m0, n0, b_proj, out);
        return;
    }

    // ------------------- flash role -------------------
    const int wid  = tid >> 5;
    const int lane = tid & 31;
    const int gid  = lane >> 2;
    const int tig  = lane & 3;
    const int qt   = 15 - (bid >> 5);        // heavy tiles dispatched first
    const int bh   = bid & 31;
    const int q0   = qt * 128;

    const __half* Qg = g_Qh + (size_t)bh * S_LEN * HDIM;
    const __half* Kg = g_Kh + (size_t)bh * S_LEN * HDIM;
    const __half* Vg = g_Vh + (size_t)bh * S_LEN * HDIM;

    const int lsel  = lane >> 3;
    const int lrow8 = lane & 7;
    const int aRow    = wid * 16 + ((lsel & 1) << 3) + lrow8;
    const int aColOff = (lsel >> 1) << 4;
    const int bRow    = ((lsel >> 1) << 3) + lrow8;
    const int bColOff = (lsel & 1) << 4;
    const int vRow    = ((lsel & 1) << 3) + lrow8;
    const int vColOff = (lsel >> 1) << 4;

    {
        const int r = tid >> 1, c0 = (tid & 1) * 4;
        const __half* gq = Qg + (size_t)(q0 + r) * HDIM;
#pragma unroll
        for (int c = 0; c < 4; c++)
            cp16(sb + swz(r, (c0 + c) * 16), gq + (c0 + c) * 8);
    }

#define ISSUE_KV(kt_)                                                          \
    {                                                                          \
        const int buf_ = (kt_) % 3;                                            \
        const int r = tid >> 2, c0 = (tid & 3) * 2;                            \
        const __half* gk = Kg + (size_t)((kt_) * 64 + r) * HDIM;               \
        const __half* gv = Vg + (size_t)((kt_) * 64 + r) * HDIM;               \
        _Pragma("unroll")                                                      \
        for (int c = 0; c < 2; c++) {                                          \
            cp16(sb + KOFF + buf_ * FK_BY + swz(r, (c0 + c) * 16),             \
                 gk + (c0 + c) * 8);                                           \
            cp16(sb + VOFF + buf_ * FK_BY + swz(r, (c0 + c) * 16),             \
                 gv + (c0 + c) * 8);                                           \
        }                                                                      \
    }

    const int nkt = 2 * (qt + 1);

    ISSUE_KV(0);
    asm volatile("cp.async.commit_group;" ::: "memory");
    if (nkt > 1) ISSUE_KV(1);
    asm volatile("cp.async.commit_group;" ::: "memory");
    asm volatile("cp.async.wait_group 1;" ::: "memory");
    __syncthreads();

    uint32_t qa[4][4];
#pragma unroll
    for (int g = 0; g < 4; g++)
        LDSM_X4(qa[g][0], qa[g][1], qa[g][2], qa[g][3],
                sb + swz(aRow, 32 * g + aColOff));

    float m0v = -1e30f, m1v = -1e30f, l0 = 0.0f, l1 = 0.0f;
    float o[8][4];
#pragma unroll
    for (int nt = 0; nt < 8; nt++)
#pragma unroll
        for (int r = 0; r < 4; r++) o[nt][r] = 0.0f;

    const int r0g = q0 + wid * 16 + gid;

    for (int kt = 0; kt < nkt; kt++) {
        if (kt > 0) {
            asm volatile("cp.async.wait_group 1;" ::: "memory");
            __syncthreads();
        }
        if (kt + 2 < nkt) ISSUE_KV(kt + 2);
        asm volatile("cp.async.commit_group;" ::: "memory");

        const uint32_t Ks = sb + KOFF + (uint32_t)((kt % 3) * FK_BY);
        const uint32_t Vs = sb + VOFF + (uint32_t)((kt % 3) * FK_BY);
        const int k0 = kt * 64;

        float s[8][4];
#pragma unroll
        for (int nt = 0; nt < 8; nt++)
#pragma unroll
            for (int r = 0; r < 4; r++) s[nt][r] = 0.0f;

#pragma unroll
        for (int g = 0; g < 4; g++) {
            const int bc = 32 * g;
#pragma unroll
            for (int np = 0; np < 4; np++) {
                uint32_t bf[4];
                LDSM_X4(bf[0], bf[1], bf[2], bf[3],
                        Ks + swz(bRow + np * 16, bc + bColOff));
                mma_f16(s[2 * np][0], s[2 * np][1], s[2 * np][2], s[2 * np][3],
                        qa[g][0], qa[g][1], qa[g][2], qa[g][3], bf[0], bf[1]);
                mma_f16(s[2 * np + 1][0], s[2 * np + 1][1],
                        s[2 * np + 1][2], s[2 * np + 1][3],
                        qa[g][0], qa[g][1], qa[g][2], qa[g][3], bf[2], bf[3]);
            }
        }

        // Q pre-scaled: S already in log2 domain. Only mask.
        const bool domask = (k0 + 63) > r0g;
        if (domask) {
#pragma unroll
            for (int nt = 0; nt < 8; nt++) {
                const int c0 = k0 + nt * 8 + tig * 2;
                if (c0 > r0g)         s[nt][0] = -1e30f;
                if (c0 + 1 > r0g)     s[nt][1] = -1e30f;
                if (c0 > r0g + 8)     s[nt][2] = -1e30f;
                if (c0 + 1 > r0g + 8) s[nt][3] = -1e30f;
            }
        }

        float mx0 = -1e30f, mx1 = -1e30f;
#pragma unroll
        for (int nt = 0; nt < 8; nt++) {
            mx0 = fmaxf(mx0, fmaxf(s[nt][0], s[nt][1]));
            mx1 = fmaxf(mx1, fmaxf(s[nt][2], s[nt][3]));
        }
        mx0 = fmaxf(mx0, __shfl_xor_sync(0xffffffffu, mx0, 1));
        mx0 = fmaxf(mx0, __shfl_xor_sync(0xffffffffu, mx0, 2));
        mx1 = fmaxf(mx1, __shfl_xor_sync(0xffffffffu, mx1, 1));
        mx1 = fmaxf(mx1, __shfl_xor_sync(0xffffffffu, mx1, 2));

        const float mn0 = fmaxf(m0v, mx0);
        const float mn1 = fmaxf(m1v, mx1);
        const float al0 = ex2(m0v - mn0);
        const float al1 = ex2(m1v - mn1);
        m0v = mn0; m1v = mn1;

        uint32_t ph[8][2];
        float sum0 = 0.0f, sum1 = 0.0f;
#pragma unroll
        for (int nt = 0; nt < 8; nt++) {
            __half2 h01 = __floats2half2_rn(ex2(s[nt][0] - mn0),
                                            ex2(s[nt][1] - mn0));
            __half2 h23 = __floats2half2_rn(ex2(s[nt][2] - mn1),
                                            ex2(s[nt][3] - mn1));
            ph[nt][0] = h2u(h01);
            ph[nt][1] = h2u(h23);
            float2 f01 = __half22float2(h01);
            float2 f23 = __half22float2(h23);
            sum0 += f01.x + f01.y;
            sum1 += f23.x + f23.y;
        }
        sum0 += __shfl_xor_sync(0xffffffffu, sum0, 1);
        sum0 += __shfl_xor_sync(0xffffffffu, sum0, 2);
        sum1 += __shfl_xor_sync(0xffffffffu, sum1, 1);
        sum1 += __shfl_xor_sync(0xffffffffu, sum1, 2);
        l0 = l0 * al0 + sum0;
        l1 = l1 * al1 + sum1;

#pragma unroll
        for (int nt = 0; nt < 8; nt++) {
            o[nt][0] *= al0; o[nt][1] *= al0;
            o[nt][2] *= al1; o[nt][3] *= al1;
        }

#pragma unroll
        for (int g = 0; g < 4; g++) {
#pragma unroll
            for (int np = 0; np < 4; np++) {
                uint32_t bf[4];
                LDSM_X4_T(bf[0], bf[1], bf[2], bf[3],
                          Vs + swz(16 * g + vRow, np * 32 + vColOff));
                mma_f16(o[2 * np][0], o[2 * np][1], o[2 * np][2], o[2 * np][3],
                        ph[2 * g][0], ph[2 * g][1],
                        ph[2 * g + 1][0], ph[2 * g + 1][1], bf[0], bf[1]);
                mma_f16(o[2 * np + 1][0], o[2 * np + 1][1],
                        o[2 * np + 1][2], o[2 * np + 1][3],
                        ph[2 * g][0], ph[2 * g][1],
                        ph[2 * g + 1][0], ph[2 * g + 1][1], bf[2], bf[3]);
            }
        }
    }
#undef ISSUE_KV

    // write ctx fp16, then signal completion of (batch,qtile) for this head
    const int b = bh >> 4, h = bh & 15;
    const float inv0 = 1.0f / l0;
    const float inv1 = 1.0f / l1;
    const int r1g = r0g + 8;
#pragma unroll
    for (int nt = 0; nt < 8; nt++) {
        const int col = h * HDIM + nt * 8 + tig * 2;
        *(__half2*)(g_CTXh + ((size_t)(b * S_LEN + r0g)) * EMB + col)
            = __floats2half2_rn(o[nt][0] * inv0, o[nt][1] * inv0);
        *(__half2*)(g_CTXh + ((size_t)(b * S_LEN + r1g)) * EMB + col)
            = __floats2half2_rn(o[nt][2] * inv1, o[nt][3] * inv1);
    }
    __threadfence();
    __syncthreads();
    if (tid == 0) atomicAdd(&g_ctr[b * 16 + qt], 1);
}

// ---------------------------------------------------------------------------
extern "C" void kernel_launch(void* const* d_in, const int* in_sizes, int n_in,
                              void* d_out, int out_size)
{
    const float* x      = (const float*)d_in[0];
    const float* w_attn = (const float*)d_in[1];
    const float* b_attn = (const float*)d_in[2];
    const float* w_proj = (const float*)d_in[3];
    const float* b_proj = (const float*)d_in[4];
    float* out = (float*)d_out;

    cudaFuncSetAttribute(gemm_qkv,  cudaFuncAttributeMaxDynamicSharedMemorySize, GSMEM_BYTES);
    cudaFuncSetAttribute(flash_proj, cudaFuncAttributeMaxDynamicSharedMemorySize, FUSED_SMEM);

    // 0) prep: x->fp16, weight transposes, counter reset
    prep_all<<<PREP_BLOCKS, 256>>>(x, w_attn, w_proj);

    // 1) QKV GEMM (persistent) -> Q(scaled)/K/V fp16
    gemm_qkv<<<GRID_PERSIST, 256, GSMEM_BYTES>>>(b_attn);

    // 2+3) fused: flash attention (bids 0-511) + projection (bids 512-767)
    flash_proj<<<768, 256, FUSED_SMEM>>>(b_proj, out);
}

// round 17
// speedup vs baseline: 1.1569x; 1.0225x over previous
#include <cuda_runtime.h>
#include <cuda_fp16.h>
#include <cstdint>
#include <math.h>

// Problem constants
#define B_SZ   2
#define S_LEN  2048
#define EMB    1024
#define NHEAD  16
#define HDIM   64
#define ROWS   (B_SZ * S_LEN)          // 4096

// Scratch (device globals -> no allocation). All fp16 operand tensors.
__device__ __half g_Qh [B_SZ * NHEAD * S_LEN * HDIM];   // [b,h,s,d], PRE-SCALED by SCALE2
__device__ __half g_Kh [B_SZ * NHEAD * S_LEN * HDIM];
__device__ __half g_Vh [B_SZ * NHEAD * S_LEN * HDIM];
__device__ __half g_CTXh[ROWS * EMB];
__device__ __half g_Xh  [ROWS * EMB];
__device__ __half g_WaTh[3 * EMB * EMB];                // w_attn^T [3072][1024]
__device__ __half g_WpTh[EMB * EMB];                    // w_proj^T [1024][1024]
__device__ int    g_ctrA[32];           // per qkv m-tile: n-tiles done (target 24)
__device__ int    g_ctr [32];           // per ctx 128-row tile: heads done (target 16)

#define SCALE2 0.18033688011112042f     // 0.125 * log2(e)

// ---------------------------------------------------------------------------
// Helpers
// ---------------------------------------------------------------------------
__device__ __forceinline__ uint32_t smem_u32(const void* p) {
    uint32_t a;
    asm("{ .reg .u64 t; cvta.to.shared.u64 t, %1; cvt.u32.u64 %0, t; }"
        : "=r"(a) : "l"(p));
    return a;
}
__device__ __forceinline__ void cp16(uint32_t smaddr, const void* gaddr) {
    asm volatile("cp.async.cg.shared.global [%0], [%1], 16;"
                 :: "r"(smaddr), "l"(gaddr) : "memory");
}
__device__ __forceinline__ uint32_t h2u(__half2 h) {
    return *reinterpret_cast<uint32_t*>(&h);
}
__device__ __forceinline__ float ex2(float x) {
    float y;
    asm("ex2.approx.ftz.f32 %0, %1;" : "=f"(y) : "f"(x));
    return y;
}
__device__ __forceinline__ void mma_f16(float& d0, float& d1, float& d2, float& d3,
                                        uint32_t a0, uint32_t a1, uint32_t a2, uint32_t a3,
                                        uint32_t b0, uint32_t b1) {
    asm volatile(
        "mma.sync.aligned.m16n8k16.row.col.f32.f16.f16.f32 "
        "{%0,%1,%2,%3},{%4,%5,%6,%7},{%8,%9},{%0,%1,%2,%3};"
        : "+f"(d0), "+f"(d1), "+f"(d2), "+f"(d3)
        : "r"(a0), "r"(a1), "r"(a2), "r"(a3), "r"(b0), "r"(b1));
}
#define LDSM_X4(r0, r1, r2, r3, addr)                                          \
    asm volatile("ldmatrix.sync.aligned.m8n8.x4.shared.b16 {%0,%1,%2,%3}, [%4];" \
                 : "=r"(r0), "=r"(r1), "=r"(r2), "=r"(r3) : "r"(addr))
#define LDSM_X4_T(r0, r1, r2, r3, addr)                                        \
    asm volatile("ldmatrix.sync.aligned.m8n8.x4.trans.shared.b16 {%0,%1,%2,%3}, [%4];" \
                 : "=r"(r0), "=r"(r1), "=r"(r2), "=r"(r3) : "r"(addr))

__device__ __forceinline__ uint32_t swz(int row, int bc) {
    return (uint32_t)(row * 128 + (((bc >> 4) ^ (row & 7)) << 4) + (bc & 15));
}

// ---------------------------------------------------------------------------
// Fused prep: x -> fp16, weight transposes, counter reset.
// ---------------------------------------------------------------------------
#define PREP_CVT_BLOCKS 4096
#define PREP_WA_BLOCKS  3072
#define PREP_WP_BLOCKS  1024
#define PREP_BLOCKS (PREP_CVT_BLOCKS + PREP_WA_BLOCKS + PREP_WP_BLOCKS)

__global__ void prep_all(const float* __restrict__ x,
                         const float* __restrict__ w_attn,
                         const float* __restrict__ w_proj)
{
    const int bid = blockIdx.x;
    if (bid == 0 && threadIdx.x < 32) {
        g_ctrA[threadIdx.x] = 0;
        g_ctr[threadIdx.x]  = 0;
    }
    if (bid < PREP_CVT_BLOCKS) {
        int i = (bid * 256 + threadIdx.x) * 4;
        float4 v = *(const float4*)(x + i);
        __half2* o = (__half2*)(g_Xh + i);
        o[0] = __floats2half2_rn(v.x, v.y);
        o[1] = __floats2half2_rn(v.z, v.w);
        return;
    }
    __shared__ float t[32][33];
    const float* src;
    __half* dst;
    int N, nblk_x, tb;
    if (bid < PREP_CVT_BLOCKS + PREP_WA_BLOCKS) {
        tb = bid - PREP_CVT_BLOCKS;
        src = w_attn; dst = g_WaTh; N = 3 * EMB; nblk_x = (3 * EMB) / 32;
    } else {
        tb = bid - PREP_CVT_BLOCKS - PREP_WA_BLOCKS;
        src = w_proj; dst = g_WpTh; N = EMB; nblk_x = EMB / 32;
    }
    const int K = EMB;
    const int x_ = threadIdx.x & 31, y_ = threadIdx.x >> 5;
    const int n0 = (tb % nblk_x) * 32, k0 = (tb / nblk_x) * 32;
#pragma unroll
    for (int i = 0; i < 4; i++)
        t[y_ + i * 8][x_] = src[(size_t)(k0 + y_ + i * 8) * N + n0 + x_];
    __syncthreads();
#pragma unroll
    for (int i = 0; i < 4; i++)
        dst[(size_t)(n0 + y_ + i * 8) * K + k0 + x_] = __float2half_rn(t[x_][y_ + i * 8]);
}

// ---------------------------------------------------------------------------
// GEMM tiling constants
// ---------------------------------------------------------------------------
#define CMM 128
#define CNN 128
#define TKK 64
#define A_BY (CMM * TKK * 2)            // 16384
#define STG_B (2 * A_BY)                // 32768
#define SPIPE 3
#define GSMEM_BYTES (SPIPE * STG_B)     // 98304
#define NSTAGE (EMB / TKK)              // 16

// GEMM mainloop+epilogue as a device function (R10/R12-proven shape).
// MODE 0: A=g_Xh, BT=g_WaTh -> Q(pre-scaled)/K/V fp16. MODE 1: ctx @ WpT -> out.
template <int MODE>
__device__ __forceinline__ void gemm_tile_body(
    const uint32_t sb, char* smc, int m0, int n0,
    const float* __restrict__ bias, float* __restrict__ Cout)
{
    const int tid  = threadIdx.x;
    const int wid  = tid >> 5;
    const int lane = tid & 31;
    const int gid  = lane >> 2;
    const int tig  = lane & 3;
    const int warp_m = (wid >> 2) * 64;
    const int warp_n = (wid & 3) * 32;

    const __half* A  = (MODE == 1) ? g_CTXh : g_Xh;
    const __half* BT = (MODE == 1) ? g_WpTh : g_WaTh;

    const int lsel  = lane >> 3;
    const int lrow8 = lane & 7;
    const int aRowL   = warp_m + ((lsel & 1) << 3) + lrow8;
    const int aColOff = (lsel >> 1) << 4;
    const int bRowL   = warp_n + ((lsel >> 1) << 3) + lrow8;
    const int bColOff = (lsel & 1) << 4;

    const int lrow = tid >> 1;
    const int cb   = (tid & 1) * 4;

    float acc[4][4][4];
#pragma unroll
    for (int mt = 0; mt < 4; mt++)
#pragma unroll
        for (int nt = 0; nt < 4; nt++)
#pragma unroll
            for (int r = 0; r < 4; r++) acc[mt][nt][r] = 0.0f;

    const __half* gA = A  + (size_t)(m0 + lrow) * EMB;
    const __half* gB = BT + (size_t)(n0 + lrow) * EMB;

#define ISSUE(s_)                                                              \
    {                                                                          \
        uint32_t st = sb + (uint32_t)(((s_) % SPIPE) * STG_B);                 \
        const __half* ga = gA + (s_) * TKK;                                    \
        const __half* gb = gB + (s_) * TKK;                                    \
        _Pragma("unroll")                                                      \
        for (int c = 0; c < 4; c++) {                                          \
            cp16(st + swz(lrow, (cb + c) * 16), ga + (cb + c) * 8);            \
            cp16(st + A_BY + swz(lrow, (cb + c) * 16), gb + (cb + c) * 8);     \
        }                                                                      \
    }

    ISSUE(0); asm volatile("cp.async.commit_group;" ::: "memory");
    ISSUE(1); asm volatile("cp.async.commit_group;" ::: "memory");
    asm volatile("cp.async.wait_group 1;" ::: "memory");
    __syncthreads();

    for (int s = 0; s < NSTAGE; s++) {
        if (s + 2 < NSTAGE) ISSUE(s + 2);
        asm volatile("cp.async.commit_group;" ::: "memory");

        const uint32_t stA = sb + (uint32_t)((s % SPIPE) * STG_B);
        const uint32_t stB = stA + A_BY;
#pragma unroll
        for (int g = 0; g < 4; g++) {
            const int bc = 32 * g;
            uint32_t af[4][4], bf[2][4];
#pragma unroll
            for (int mt = 0; mt < 4; mt++)
                LDSM_X4(af[mt][0], af[mt][1], af[mt][2], af[mt][3],
                        stA + swz(aRowL + mt * 16, bc + aColOff));
#pragma unroll
            for (int np = 0; np < 2; np++)
                LDSM_X4(bf[np][0], bf[np][1], bf[np][2], bf[np][3],
                        stB + swz(bRowL + np * 16, bc + bColOff));
#pragma unroll
            for (int mt = 0; mt < 4; mt++)
#pragma unroll
                for (int nt = 0; nt < 4; nt++)
                    mma_f16(acc[mt][nt][0], acc[mt][nt][1],
                            acc[mt][nt][2], acc[mt][nt][3],
                            af[mt][0], af[mt][1], af[mt][2], af[mt][3],
                            bf[nt >> 1][(nt & 1) * 2], bf[nt >> 1][(nt & 1) * 2 + 1]);
        }
        asm volatile("cp.async.wait_group 1;" ::: "memory");
        __syncthreads();
    }
#undef ISSUE

#pragma unroll
    for (int mt = 0; mt < 4; mt++) {
        const int r0 = m0 + warp_m + mt * 16 + gid;
        const int r1 = r0 + 8;
#pragma unroll
        for (int nt = 0; nt < 4; nt++) {
            const int nb = n0 + warp_n + nt * 8;
            const int c  = nb + tig * 2;
            const float2 bv = *(const float2*)(bias + c);
            float2 o0, o1;
            o0.x = acc[mt][nt][0] + bv.x;
            o0.y = acc[mt][nt][1] + bv.y;
            o1.x = acc[mt][nt][2] + bv.x;
            o1.y = acc[mt][nt][3] + bv.y;
            if (MODE == 1) {
                *(float2*)(Cout + (size_t)r0 * EMB + c) = o0;
                *(float2*)(Cout + (size_t)r1 * EMB + c) = o1;
            } else {
                const int which = nb >> 10;
                const int e  = nb & 1023;
                const int h  = e >> 6;
                const int dd = (e & 63) + tig * 2;
                const int b0i = r0 >> 11, s0i = r0 & 2047;
                const int b1i = r1 >> 11, s1i = r1 & 2047;
                if (which == 0) {
                    o0.x *= SCALE2; o0.y *= SCALE2;
                    o1.x *= SCALE2; o1.y *= SCALE2;
                }
                __half* dst = (which == 0) ? g_Qh : (which == 1) ? g_Kh : g_Vh;
                *(__half2*)(dst + ((size_t)(b0i * NHEAD + h) * S_LEN + s0i) * HDIM + dd)
                    = __floats2half2_rn(o0.x, o0.y);
                *(__half2*)(dst + ((size_t)(b1i * NHEAD + h) * S_LEN + s1i) * HDIM + dd)
                    = __floats2half2_rn(o1.x, o1.y);
            }
        }
    }
}

// ---------------------------------------------------------------------------
// Mega-kernel: bids [0,768) QKV tiles -> [768,1280) flash -> [1280,1536) proj.
// Dispatch order guarantees producers precede consumers (spin-safe).
// ---------------------------------------------------------------------------
#define FQ_BY (128 * 128)
#define FK_BY (64 * 128)
#define KOFF  FQ_BY
#define VOFF  (FQ_BY + 3 * FK_BY)
#define FUSED_SMEM GSMEM_BYTES          // 96KB >= flash's 64KB

__constant__ int c_qtseq[16] = {15, 0, 14, 1, 13, 2, 12, 3,
                                11, 4, 10, 5, 9, 6, 8, 7};

__global__ void __launch_bounds__(256, 2)
mega(const float* __restrict__ b_attn,
     const float* __restrict__ b_proj, float* __restrict__ out)
{
    extern __shared__ char smc[];
    const uint32_t sb = smem_u32(smc);
    const int bid = blockIdx.x;
    const int tid = threadIdx.x;

    if (bid < 768) {
        // ------------------- QKV GEMM role -------------------
        const int j  = bid / 24;             // 0..31
        const int n0 = (bid % 24) * CNN;
        const int mtile = (j & 1) * 16 + (j >> 1);   // interleave batches
        gemm_tile_body<0>(sb, smc, mtile * CMM, n0, b_attn, nullptr);
        __threadfence();
        __syncthreads();
        if (tid == 0) atomicAdd(&g_ctrA[mtile], 1);
        return;
    }

    if (bid >= 1280) {
        // ------------------- projection role -------------------
        const int t  = bid - 1280;           // 0..255
        const int j  = t >> 3;               // 0..31
        const int n0 = (t & 7) * CNN;
        const int qt_ = c_qtseq[j >> 1];
        const int b_  = j & 1;
        const int mtile = b_ * 16 + qt_;
        if (tid == 0) {
            while (atomicAdd(&g_ctr[mtile], 0) < NHEAD) __nanosleep(200);
        }
        __syncthreads();
        __threadfence();
        gemm_tile_body<1>(sb, smc, mtile * CMM, n0, b_proj, out);
        return;
    }

    // ------------------- flash role -------------------
    const int fbid = bid - 768;              // 0..511
    const int wid  = tid >> 5;
    const int lane = tid & 31;
    const int gid  = lane >> 2;
    const int tig  = lane & 3;
    const int qt   = c_qtseq[fbid >> 5];     // heavy/light interleaved
    const int bh   = fbid & 31;
    const int q0   = qt * 128;
    const int b    = bh >> 4;

    // wait for QKV m-tiles b*16+0 .. b*16+qt (covers Q tile qt + K/V prefix)
    if (tid == 0) {
        for (int q2 = 0; q2 <= qt; q2++)
            while (atomicAdd(&g_ctrA[b * 16 + q2], 0) < 24) __nanosleep(100);
    }
    __syncthreads();
    __threadfence();

    const __half* Qg = g_Qh + (size_t)bh * S_LEN * HDIM;
    const __half* Kg = g_Kh + (size_t)bh * S_LEN * HDIM;
    const __half* Vg = g_Vh + (size_t)bh * S_LEN * HDIM;

    const int lsel  = lane >> 3;
    const int lrow8 = lane & 7;
    const int aRow    = wid * 16 + ((lsel & 1) << 3) + lrow8;
    const int aColOff = (lsel >> 1) << 4;
    const int bRow    = ((lsel >> 1) << 3) + lrow8;
    const int bColOff = (lsel & 1) << 4;
    const int vRow    = ((lsel & 1) << 3) + lrow8;
    const int vColOff = (lsel >> 1) << 4;

    {
        const int r = tid >> 1, c0 = (tid & 1) * 4;
        const __half* gq = Qg + (size_t)(q0 + r) * HDIM;
#pragma unroll
        for (int c = 0; c < 4; c++)
            cp16(sb + swz(r, (c0 + c) * 16), gq + (c0 + c) * 8);
    }

#define ISSUE_KV(kt_)                                                          \
    {                                                                          \
        const int buf_ = (kt_) % 3;                                            \
        const int r = tid >> 2, c0 = (tid & 3) * 2;                            \
        const __half* gk = Kg + (size_t)((kt_) * 64 + r) * HDIM;               \
        const __half* gv = Vg + (size_t)((kt_) * 64 + r) * HDIM;               \
        _Pragma("unroll")                                                      \
        for (int c = 0; c < 2; c++) {                                          \
            cp16(sb + KOFF + buf_ * FK_BY + swz(r, (c0 + c) * 16),             \
                 gk + (c0 + c) * 8);                                           \
            cp16(sb + VOFF + buf_ * FK_BY + swz(r, (c0 + c) * 16),             \
                 gv + (c0 + c) * 8);                                           \
        }                                                                      \
    }

    const int nkt = 2 * (qt + 1);

    ISSUE_KV(0);
    asm volatile("cp.async.commit_group;" ::: "memory");
    if (nkt > 1) ISSUE_KV(1);
    asm volatile("cp.async.commit_group;" ::: "memory");
    asm volatile("cp.async.wait_group 1;" ::: "memory");
    __syncthreads();

    uint32_t qa[4][4];
#pragma unroll
    for (int g = 0; g < 4; g++)
        LDSM_X4(qa[g][0], qa[g][1], qa[g][2], qa[g][3],
                sb + swz(aRow, 32 * g + aColOff));

    float m0v = -1e30f, m1v = -1e30f, l0 = 0.0f, l1 = 0.0f;
    float o[8][4];
#pragma unroll
    for (int nt = 0; nt < 8; nt++)
#pragma unroll
        for (int r = 0; r < 4; r++) o[nt][r] = 0.0f;

    const int r0g = q0 + wid * 16 + gid;

    for (int kt = 0; kt < nkt; kt++) {
        if (kt > 0) {
            asm volatile("cp.async.wait_group 1;" ::: "memory");
            __syncthreads();
        }
        if (kt + 2 < nkt) ISSUE_KV(kt + 2);
        asm volatile("cp.async.commit_group;" ::: "memory");

        const uint32_t Ks = sb + KOFF + (uint32_t)((kt % 3) * FK_BY);
        const uint32_t Vs = sb + VOFF + (uint32_t)((kt % 3) * FK_BY);
        const int k0 = kt * 64;

        float s[8][4];
#pragma unroll
        for (int nt = 0; nt < 8; nt++)
#pragma unroll
            for (int r = 0; r < 4; r++) s[nt][r] = 0.0f;

#pragma unroll
        for (int g = 0; g < 4; g++) {
            const int bc = 32 * g;
#pragma unroll
            for (int np = 0; np < 4; np++) {
                uint32_t bf[4];
                LDSM_X4(bf[0], bf[1], bf[2], bf[3],
                        Ks + swz(bRow + np * 16, bc + bColOff));
                mma_f16(s[2 * np][0], s[2 * np][1], s[2 * np][2], s[2 * np][3],
                        qa[g][0], qa[g][1], qa[g][2], qa[g][3], bf[0], bf[1]);
                mma_f16(s[2 * np + 1][0], s[2 * np + 1][1],
                        s[2 * np + 1][2], s[2 * np + 1][3],
                        qa[g][0], qa[g][1], qa[g][2], qa[g][3], bf[2], bf[3]);
            }
        }

        const bool domask = (k0 + 63) > r0g;
        if (domask) {
#pragma unroll
            for (int nt = 0; nt < 8; nt++) {
                const int c0 = k0 + nt * 8 + tig * 2;
                if (c0 > r0g)         s[nt][0] = -1e30f;
                if (c0 + 1 > r0g)     s[nt][1] = -1e30f;
                if (c0 > r0g + 8)     s[nt][2] = -1e30f;
                if (c0 + 1 > r0g + 8) s[nt][3] = -1e30f;
            }
        }

        float mx0 = -1e30f, mx1 = -1e30f;
#pragma unroll
        for (int nt = 0; nt < 8; nt++) {
            mx0 = fmaxf(mx0, fmaxf(s[nt][0], s[nt][1]));
            mx1 = fmaxf(mx1, fmaxf(s[nt][2], s[nt][3]));
        }
        mx0 = fmaxf(mx0, __shfl_xor_sync(0xffffffffu, mx0, 1));
        mx0 = fmaxf(mx0, __shfl_xor_sync(0xffffffffu, mx0, 2));
        mx1 = fmaxf(mx1, __shfl_xor_sync(0xffffffffu, mx1, 1));
        mx1 = fmaxf(mx1, __shfl_xor_sync(0xffffffffu, mx1, 2));

        const float mn0 = fmaxf(m0v, mx0);
        const float mn1 = fmaxf(m1v, mx1);
        const float al0 = ex2(m0v - mn0);
        const float al1 = ex2(m1v - mn1);
        m0v = mn0; m1v = mn1;

        uint32_t ph[8][2];
        float sum0 = 0.0f, sum1 = 0.0f;
#pragma unroll
        for (int nt = 0; nt < 8; nt++) {
            __half2 h01 = __floats2half2_rn(ex2(s[nt][0] - mn0),
                                            ex2(s[nt][1] - mn0));
            __half2 h23 = __floats2half2_rn(ex2(s[nt][2] - mn1),
                                            ex2(s[nt][3] - mn1));
            ph[nt][0] = h2u(h01);
            ph[nt][1] = h2u(h23);
            float2 f01 = __half22float2(h01);
            float2 f23 = __half22float2(h23);
            sum0 += f01.x + f01.y;
            sum1 += f23.x + f23.y;
        }
        sum0 += __shfl_xor_sync(0xffffffffu, sum0, 1);
        sum0 += __shfl_xor_sync(0xffffffffu, sum0, 2);
        sum1 += __shfl_xor_sync(0xffffffffu, sum1, 1);
        sum1 += __shfl_xor_sync(0xffffffffu, sum1, 2);
        l0 = l0 * al0 + sum0;
        l1 = l1 * al1 + sum1;

#pragma unroll
        for (int nt = 0; nt < 8; nt++) {
            o[nt][0] *= al0; o[nt][1] *= al0;
            o[nt][2] *= al1; o[nt][3] *= al1;
        }

#pragma unroll
        for (int g = 0; g < 4; g++) {
#pragma unroll
            for (int np = 0; np < 4; np++) {
                uint32_t bf[4];
                LDSM_X4_T(bf[0], bf[1], bf[2], bf[3],
                          Vs + swz(16 * g + vRow, np * 32 + vColOff));
                mma_f16(o[2 * np][0], o[2 * np][1], o[2 * np][2], o[2 * np][3],
                        ph[2 * g][0], ph[2 * g][1],
                        ph[2 * g + 1][0], ph[2 * g + 1][1], bf[0], bf[1]);
                mma_f16(o[2 * np + 1][0], o[2 * np + 1][1],
                        o[2 * np + 1][2], o[2 * np + 1][3],
                        ph[2 * g][0], ph[2 * g][1],
                        ph[2 * g + 1][0], ph[2 * g + 1][1], bf[2], bf[3]);
            }
        }
    }
#undef ISSUE_KV

    // write ctx fp16, then signal completion for this head
    const int h = bh & 15;
    const float inv0 = 1.0f / l0;
    const float inv1 = 1.0f / l1;
    const int r1g = r0g + 8;
#pragma unroll
    for (int nt = 0; nt < 8; nt++) {
        const int col = h * HDIM + nt * 8 + tig * 2;
        *(__half2*)(g_CTXh + ((size_t)(b * S_LEN + r0g)) * EMB + col)
            = __floats2half2_rn(o[nt][0] * inv0, o[nt][1] * inv0);
        *(__half2*)(g_CTXh + ((size_t)(b * S_LEN + r1g)) * EMB + col)
            = __floats2half2_rn(o[nt][2] * inv1, o[nt][3] * inv1);
    }
    __threadfence();
    __syncthreads();
    if (tid == 0) atomicAdd(&g_ctr[b * 16 + qt], 1);
}

// ---------------------------------------------------------------------------
extern "C" void kernel_launch(void* const* d_in, const int* in_sizes, int n_in,
                              void* d_out, int out_size)
{
    const float* x      = (const float*)d_in[0];
    const float* w_attn = (const float*)d_in[1];
    const float* b_attn = (const float*)d_in[2];
    const float* w_proj = (const float*)d_in[3];
    const float* b_proj = (const float*)d_in[4];
    float* out = (float*)d_out;

    cudaFuncSetAttribute(mega, cudaFuncAttributeMaxDynamicSharedMemorySize, FUSED_SMEM);

    // 0) prep: x->fp16, weight transposes, counter reset
    prep_all<<<PREP_BLOCKS, 256>>>(x, w_attn, w_proj);

    // 1) mega-kernel: QKV GEMM -> flash attention -> projection
    mega<<<1536, 256, FUSED_SMEM>>>(b_attn, b_proj, out);
}